// round 9
// baseline (speedup 1.0000x reference)
#include <cuda_runtime.h>
#include <math.h>
#include <stdint.h>

#define T_STEPS 64
#define NN 16384
#define NE 262144
#define F_IN 8
#define H1 12
#define C1 16
#define HID 192
#define CAP0 256
#define MAX_SLOTS 64
#define CAPE 4096
#define LOCAL_CAP 128

// ---------------- scratch (static device globals; zero-initialized at load) ----------------
__device__ int   g_cnt0[T_STEPS];
__device__ int   g_e0[T_STEPS][CAP0];     // raw (atomic order) from pass1
__device__ int   g_s0[T_STEPS][CAP0];
__device__ int   g_e0s[T_STEPS][CAP0];    // canonical sorted copies (written by pass2 block0)
__device__ int   g_s0s[T_STEPS][CAP0];
__device__ int   g_slot0[T_STEPS][CAP0];
__device__ int   g_n0[T_STEPS];
__device__ int   g_scnt[T_STEPS];
__device__ int   g_S[T_STEPS][MAX_SLOTS];
__device__ int   g_incnt[T_STEPS];
__device__ int   g_ie_e[T_STEPS][CAPE];
__device__ int   g_ie_src[T_STEPS][CAPE];
__device__ int   g_ie_dst[T_STEPS][CAPE];
__device__ float g_xl2[T_STEPS][MAX_SLOTS];
__device__ float g_series[T_STEPS];
__device__ int   g_done3[T_STEPS];

__device__ __forceinline__ float lrelu(float x) { return x > 0.f ? x : 0.2f * x; }
__device__ __forceinline__ float sigm(float x) { return 1.f / (1.f + expf(-x)); }

// ---- packed fp32x2 FMA (sm_103a) ----
typedef unsigned long long ull;
__device__ __forceinline__ void fma2(ull& acc, ull w, ull h) {
    asm("fma.rn.f32x2 %0, %1, %2, %0;" : "+l"(acc) : "l"(w), "l"(h));
}
__device__ __forceinline__ ull pk2(float x, float y) {
    ull r; asm("mov.b64 %0, {%1, %2};" : "=l"(r) : "f"(x), "f"(y)); return r;
}
__device__ __forceinline__ float upksum(ull a) {
    float x, y; asm("mov.b64 {%0, %1}, %2;" : "=f"(x), "=f"(y) : "l"(a)); return x + y;
}

__device__ __forceinline__ void edit_factor(int e, float& mul, float& add) {
    mul = 1.f; add = 0.f;
    if (e >= 0 && e < 23) {
        switch (e) {
            case 1: case 2: case 12: case 17: case 19: case 22: mul = 0.9f; break;
            case 7: case 14: mul = 0.9f; add = 0.1f; break;
            case 10: case 13: mul = 0.9f; add = 0.05f; break;
            default: break;
        }
    }
}

// ------------- K1: find edges with dst == 0 (16 vals/thread, min-tree) -------------
__global__ void k_pass1(const int* __restrict__ ei) {
    const int t = blockIdx.y;
    const int* __restrict__ src = ei + (size_t)t * 2 * NE;
    const int* __restrict__ dst = src + NE;
    const int e0 = blockIdx.x * (256 * 16) + threadIdx.x * 16;
    int4 v0 = *(const int4*)(dst + e0);
    int4 v1 = *(const int4*)(dst + e0 + 4);
    int4 v2 = *(const int4*)(dst + e0 + 8);
    int4 v3 = *(const int4*)(dst + e0 + 12);
    int m0 = min(min(v0.x, v0.y), min(v0.z, v0.w));
    int m1 = min(min(v1.x, v1.y), min(v1.z, v1.w));
    int m2 = min(min(v2.x, v2.y), min(v2.z, v2.w));
    int m3 = min(min(v3.x, v3.y), min(v3.z, v3.w));
    if (min(min(m0, m1), min(m2, m3)) == 0) {
        int vals[16] = { v0.x, v0.y, v0.z, v0.w, v1.x, v1.y, v1.z, v1.w,
                         v2.x, v2.y, v2.z, v2.w, v3.x, v3.y, v3.z, v3.w };
        #pragma unroll
        for (int k = 0; k < 16; k++) {
            if (vals[k] == 0) {
                int p = atomicAdd(&g_cnt0[t], 1);
                if (p < CAP0) { g_e0[t][p] = e0 + k; g_s0[t][p] = src[e0 + k]; }
            }
        }
    }
}

// -- K2: edges into frontier set (page filter + byte-map; canonical build merged in) --
__global__ void k_pass2(const int* __restrict__ ei) {
    __shared__ unsigned char bmap[NN];   // 16 KB membership byte map
    __shared__ unsigned pagef[2];        // 64-bit page filter (256-node pages)
    const int t = blockIdx.y;
    {
        int4* bm4 = (int4*)bmap;
        int4 z = make_int4(0, 0, 0, 0);
        for (int i = threadIdx.x; i < NN / 16; i += 256) bm4[i] = z;
    }
    if (threadIdx.x < 2) pagef[threadIdx.x] = 0;
    __syncthreads();
    int n = g_cnt0[t]; if (n > CAP0) n = CAP0;
    if (threadIdx.x < n) {
        int s = g_s0[t][threadIdx.x];
        bmap[s] = 1;
        unsigned pg = (unsigned)s >> 8;
        atomicOr(&pagef[pg >> 5], 1u << (pg & 31));
    }
    if (threadIdx.x == 0) {               // node 0 itself
        bmap[0] = 1;
        atomicOr(&pagef[0], 1u);
    }

    // block x==0, thread 0: build canonical sorted structures (separate arrays -> no race)
    if (blockIdx.x == 0 && threadIdx.x == 0) {
        int le[CAP0], ls[CAP0];
        for (int i = 0; i < n; i++) { le[i] = g_e0[t][i]; ls[i] = g_s0[t][i]; }
        for (int i = 1; i < n; i++) {
            int ke = le[i], ks = ls[i], j = i - 1;
            while (j >= 0 && le[j] > ke) { le[j + 1] = le[j]; ls[j + 1] = ls[j]; j--; }
            le[j + 1] = ke; ls[j + 1] = ks;
        }
        int sc = 1;
        g_S[t][0] = 0;
        for (int i = 0; i < n; i++) {
            int s = ls[i], slot = -1;
            for (int j = 0; j < sc; j++) if (g_S[t][j] == s) { slot = j; break; }
            if (slot < 0 && sc < MAX_SLOTS) { g_S[t][sc] = s; slot = sc; sc++; }
            g_slot0[t][i] = slot;
            g_e0s[t][i] = le[i]; g_s0s[t][i] = ls[i];
        }
        g_scnt[t] = sc;
        g_n0[t] = n;
    }
    __syncthreads();
    const unsigned pf0 = pagef[0], pf1 = pagef[1];

    const int* __restrict__ src = ei + (size_t)t * 2 * NE;
    const int* __restrict__ dst = src + NE;
    const int e0 = blockIdx.x * (256 * 16) + threadIdx.x * 16;
    int4 v0 = *(const int4*)(dst + e0);
    int4 v1 = *(const int4*)(dst + e0 + 4);
    int4 v2 = *(const int4*)(dst + e0 + 8);
    int4 v3 = *(const int4*)(dst + e0 + 12);
    int vals[16] = { v0.x, v0.y, v0.z, v0.w, v1.x, v1.y, v1.z, v1.w,
                     v2.x, v2.y, v2.z, v2.w, v3.x, v3.y, v3.z, v3.w };
    #pragma unroll
    for (int k = 0; k < 16; k++) {
        int d = vals[k];
        unsigned pg = (unsigned)d >> 8;
        unsigned w = (pg >= 32) ? pf1 : pf0;
        if ((w >> (pg & 31)) & 1u) {
            if (bmap[d]) {
                int p = atomicAdd(&g_incnt[t], 1);
                if (p < CAPE) { g_ie_e[t][p] = e0 + k; g_ie_src[t][p] = src[e0 + k]; g_ie_dst[t][p] = d; }
            }
        }
    }
}

// ==== K3: GAT layer 1 at frontier nodes (+ fused layer-2 in last-finishing block) ====
__global__ void k_gat1(const float* __restrict__ x, const float* __restrict__ Wl1,
                       const float* __restrict__ attl1, const float* __restrict__ attr1,
                       const float* __restrict__ b1, const float* __restrict__ Wl2,
                       const float* __restrict__ attl2, const float* __restrict__ attr2,
                       const float* __restrict__ b2) {
    int t = blockIdx.y;
    int slot = blockIdx.x;
    int tid = threadIdx.x;              // 192 threads

    __shared__ float sWl[F_IN * HID];
    __shared__ float sAl[HID], sAr[HID], sB[HID], sW2[HID];
    __shared__ int   se[LOCAL_CAP], ss[LOCAL_CAP];
    __shared__ float sxr[LOCAL_CAP][F_IN];
    __shared__ float sal[LOCAL_CAP][H1];
    __shared__ float sm_[H1], sden[H1], sarU[H1];
    __shared__ float sfmul[LOCAL_CAP], sfadd[LOCAL_CAP];
    __shared__ float sred[HID];
    __shared__ int   sdeg;
    __shared__ int   sLast;
    __shared__ float l2xs[CAP0 + 1], l2a[CAP0 + 1];

    const int active = (slot < g_scnt[t]);
    if (active) {
        int u = g_S[t][slot];
        int h = tid >> 4, c = tid & 15;

        for (int i = tid; i < F_IN * HID; i += HID) sWl[i] = Wl1[i];
        sAl[tid] = attl1[tid]; sAr[tid] = attr1[tid]; sB[tid] = b1[tid]; sW2[tid] = Wl2[tid];
        if (tid == 0) sdeg = 0;
        __syncthreads();

        int cnt = g_incnt[t]; if (cnt > CAPE) cnt = CAPE;
        for (int i = tid; i < cnt; i += HID) {
            if (g_ie_dst[t][i] == u) {
                int p = atomicAdd(&sdeg, 1);
                if (p < LOCAL_CAP - 1) { se[p] = g_ie_e[t][i]; ss[p] = g_ie_src[t][i]; }
            }
        }
        __syncthreads();
        int deg = sdeg; if (deg > LOCAL_CAP - 1) deg = LOCAL_CAP - 1;
        if (tid == 0) {
            for (int i = 1; i < deg; i++) {                 // canonical order
                int ke = se[i], ks = ss[i], j = i - 1;
                while (j >= 0 && se[j] > ke) { se[j + 1] = se[j]; ss[j + 1] = ss[j]; j--; }
                se[j + 1] = ke; ss[j + 1] = ks;
            }
            se[deg] = 0x7fffffff; ss[deg] = u;              // self-loop last (never edited)
        }
        __syncthreads();
        int ndeg = deg + 1;

        for (int i = tid; i < ndeg * F_IN; i += HID)
            sxr[i >> 3][i & 7] = x[((size_t)t * NN + ss[i >> 3]) * F_IN + (i & 7)];
        __syncthreads();

        {   // ar_u from xl1[u] (self row at index deg)
            float v = 0.f;
            #pragma unroll
            for (int k = 0; k < F_IN; k++) v += sxr[deg][k] * sWl[k * HID + tid];
            float r = v * sAr[tid];
            #pragma unroll
            for (int off = 8; off; off >>= 1) r += __shfl_xor_sync(0xffffffffu, r, off, 16);
            if (c == 0) sarU[h] = r;
        }
        for (int i = 0; i < ndeg; i++) {
            float v = 0.f;
            #pragma unroll
            for (int k = 0; k < F_IN; k++) v += sxr[i][k] * sWl[k * HID + tid];
            float a = v * sAl[tid];
            #pragma unroll
            for (int off = 8; off; off >>= 1) a += __shfl_xor_sync(0xffffffffu, a, off, 16);
            if (c == 0) sal[i][h] = a;
        }
        __syncthreads();

        if (tid < H1) {
            int hh = tid;
            float m = -1e30f;
            for (int i = 0; i < ndeg; i++) { float a = lrelu(sal[i][hh] + sarU[hh]); if (a > m) m = a; }
            float den = 0.f;
            for (int i = 0; i < ndeg; i++) den += expf(lrelu(sal[i][hh] + sarU[hh]) - m);
            sm_[hh] = m; sden[hh] = den + 1e-16f;
        }
        if (tid >= 32 && tid < 32 + ndeg) {
            int i = tid - 32; float mu, ad; edit_factor(se[i], mu, ad); sfmul[i] = mu; sfadd[i] = ad;
        }
        __syncthreads();

        float acc = 0.f;
        for (int i = 0; i < ndeg; i++) {
            float a = lrelu(sal[i][h] + sarU[h]);
            float alpha = expf(a - sm_[h]) / sden[h];
            alpha = sfmul[i] * alpha + sfadd[i];
            float v = 0.f;
            #pragma unroll
            for (int k = 0; k < F_IN; k++) v += sxr[i][k] * sWl[k * HID + tid];
            acc += alpha * v;
        }
        acc += sB[tid];
        float e1 = acc > 0.f ? acc : (expf(acc) - 1.f);      // ELU
        sred[tid] = e1 * sW2[tid];
        __syncthreads();
        if (tid < 64) sred[tid] = sred[tid] + sred[tid + 64] + sred[tid + 128];
        __syncthreads();
        if (tid < 32) {
            float v = sred[tid] + sred[tid + 32];
            #pragma unroll
            for (int off = 16; off; off >>= 1) v += __shfl_xor_sync(0xffffffffu, v, off);
            if (tid == 0) g_xl2[t][slot] = v;
        }
    }

    // -------- completion counter; last block of this t runs GAT layer 2 --------
    __syncthreads();
    if (tid == 0) {
        __threadfence();
        int old = atomicAdd(&g_done3[t], 1);
        sLast = (old == gridDim.x - 1) ? 1 : 0;
        if (sLast) __threadfence();
    }
    __syncthreads();
    if (sLast) {
        int n = g_n0[t];
        if (tid < 32) {
            float al2 = attl2[0], ar2v = attr2[0];
            float x0 = *(volatile float*)&g_xl2[t][0];
            float ar0 = x0 * ar2v;
            float m = -1e30f;
            for (int i = tid; i <= n; i += 32) {
                float xs = (i < n) ? *(volatile float*)&g_xl2[t][g_slot0[t][i]] : x0;
                float a = lrelu(xs * al2 + ar0);
                l2xs[i] = xs; l2a[i] = a;
                m = fmaxf(m, a);
            }
            __syncwarp();
            #pragma unroll
            for (int off = 16; off; off >>= 1) m = fmaxf(m, __shfl_xor_sync(0xffffffffu, m, off));
            float den = 0.f;
            for (int i = tid; i <= n; i += 32) den += expf(l2a[i] - m);
            #pragma unroll
            for (int off = 16; off; off >>= 1) den += __shfl_xor_sync(0xffffffffu, den, off);
            den += 1e-16f;
            float outv = 0.f;
            for (int i = tid; i <= n; i += 32) {
                float alpha = expf(l2a[i] - m) / den;
                int e = (i < n) ? g_e0s[t][i] : 0x7fffffff;
                float mu, ad; edit_factor(e, mu, ad);
                outv += (mu * alpha + ad) * l2xs[i];
            }
            #pragma unroll
            for (int off = 16; off; off >>= 1) outv += __shfl_xor_sync(0xffffffffu, outv, off);
            if (tid == 0) {
                g_series[t] = outv + b2[0];
                // reset per-t state for next graph replay
                g_cnt0[t] = 0; g_incnt[t] = 0; g_done3[t] = 0;
            }
        }
    }
}

// ========= K4: cluster-4 LSTM, reg weights, mbarrier sync, producer nonlinearities =========
__device__ __forceinline__ int hpad(int k4) { return k4 + (k4 >> 3); }
__device__ __forceinline__ unsigned cl_rank() {
    unsigned r; asm("mov.u32 %0, %%cluster_ctarank;" : "=r"(r)); return r;
}
__device__ __forceinline__ void cl_sync() {
    asm volatile("barrier.cluster.arrive.aligned;\n\tbarrier.cluster.wait.aligned;" ::: "memory");
}
__device__ __forceinline__ void cl_store_f32(float* p, unsigned rank, float v) {
    uint32_t a = (uint32_t)__cvta_generic_to_shared(p);
    uint32_t pa;
    asm("mapa.shared::cluster.u32 %0, %1, %2;" : "=r"(pa) : "r"(a), "r"(rank));
    asm volatile("st.shared::cluster.f32 [%0], %1;" :: "r"(pa), "f"(v) : "memory");
}
__device__ __forceinline__ void mbar_arrive_remote(uint32_t mbar, unsigned rank) {
    uint32_t rem;
    asm("mapa.shared::cluster.u32 %0, %1, %2;" : "=r"(rem) : "r"(mbar), "r"(rank));
    asm volatile("mbarrier.arrive.release.cluster.shared::cluster.b64 _, [%0];"
                 :: "r"(rem) : "memory");
}
__device__ __forceinline__ void mbar_wait_cluster(uint32_t mbar, unsigned parity) {
    asm volatile(
        "{\n\t"
        ".reg .pred P1;\n\t"
        "WL_%=:\n\t"
        "mbarrier.try_wait.parity.acquire.cluster.shared::cta.b64 P1, [%0], %1, 0x989680;\n\t"
        "@P1 bra.uni WD_%=;\n\t"
        "bra.uni WL_%=;\n\t"
        "WD_%=:\n\t"
        "}"
        :: "r"(mbar), "r"(parity) : "memory");
}

__global__ void __cluster_dims__(4, 1, 1) __launch_bounds__(512, 1)
k_lstm_cl(const float* __restrict__ Wih0, const float* __restrict__ Whh0,
          const float* __restrict__ bih0, const float* __restrict__ bhh0,
          const float* __restrict__ Wih1, const float* __restrict__ Whh1,
          const float* __restrict__ bih1, const float* __restrict__ bhh1,
          const float* __restrict__ Wlin, const float* __restrict__ blin,
          float* __restrict__ out) {
    __shared__ __align__(16) float4 h0p[2][36];
    __shared__ __align__(16) float4 h1p[2][36];
    __shared__ float sg0[128], sg1[128];
    __shared__ float xs[32];
    __shared__ __align__(8) unsigned long long mbar;

    const unsigned rank = cl_rank();
    const int batch = blockIdx.x >> 2;
    const int tid = threadIdx.x;
    const int lr = tid >> 2, q = tid & 3;            // row 0..127, k-quarter
    const int gt = lr >> 5, dl = lr & 31;
    const int gr = gt * 128 + (int)rank * 32 + dl;   // global gate row
    const uint32_t mbar_a = (uint32_t)__cvta_generic_to_shared(&mbar);

    ull w0p[16], w1p[32];
    {
        const float4* W0 = (const float4*)(Whh0 + (size_t)gr * 128) + 8 * q;
        #pragma unroll
        for (int j = 0; j < 8; j++) {
            float4 w = W0[j];
            w0p[2 * j] = pk2(w.x, w.y); w0p[2 * j + 1] = pk2(w.z, w.w);
        }
        const float* Wsrc = (q < 2) ? Wih1 : Whh1;
        const float4* W1 = (const float4*)(Wsrc + (size_t)gr * 128) + 16 * (q & 1);
        #pragma unroll
        for (int j = 0; j < 16; j++) {
            float4 w = W1[j];
            w1p[2 * j] = pk2(w.x, w.y); w1p[2 * j + 1] = pk2(w.z, w.w);
        }
    }
    float wih0v = 0.f, bA = 0.f, bB = 0.f;
    if (q == 0) { wih0v = Wih0[gr]; bA = bih0[gr] + bhh0[gr]; bB = bih1[gr] + bhh1[gr]; }
    if (tid < 32) xs[tid] = g_series[batch + tid];
    {
        float* hz = (float*)&h0p[0][0];
        for (int i = tid; i < 2 * 2 * 36 * 4; i += 512) hz[i] = 0.f;
    }
    if (tid == 0) {
        asm volatile("mbarrier.init.shared.b64 [%0], %1;" :: "r"(mbar_a), "r"(256u) : "memory");
    }
    float c0 = 0.f, c1 = 0.f;
    const int hb = 16 * (q & 1);
    cl_sync();   // one full cluster barrier: mbarrier init + zeroed h visible everywhere

    for (int k = 0; k <= 32; k++) {
        const int pb = k & 1, nb = pb ^ 1;
        if (k < 32) {                     // gates0 for step k (reads h0[k-1])
            const float4* hv = h0p[pb];
            ull a0 = 0ull, a1 = 0ull;
            #pragma unroll
            for (int j = 0; j < 8; j += 2) {
                float4 ha = hv[hpad(8 * q + j)];
                float4 hbv = hv[hpad(8 * q + j + 1)];
                fma2(a0, w0p[2 * j],     *(ull*)&ha.x);
                fma2(a1, w0p[2 * j + 1], *(ull*)&ha.z);
                fma2(a0, w0p[2 * j + 2], *(ull*)&hbv.x);
                fma2(a1, w0p[2 * j + 3], *(ull*)&hbv.z);
            }
            float acc = upksum(a0) + upksum(a1);
            acc += __shfl_xor_sync(0xffffffffu, acc, 1, 4);
            acc += __shfl_xor_sync(0xffffffffu, acc, 2, 4);
            if (q == 0) {
                float gv = acc + bA + wih0v * xs[k];
                sg0[lr] = (gt == 2) ? tanhf(gv) : sigm(gv);   // producer-side nonlinearity
            }
        }
        if (k >= 1) {                     // gates1 for step k-1 (reads h0[k-1], h1[k-2])
            const float4* hsrc = (q < 2) ? h0p[pb] : h1p[pb];
            ull a0 = 0ull, a1 = 0ull;
            #pragma unroll
            for (int j = 0; j < 16; j += 2) {
                float4 ha = hsrc[hpad(hb + j)];
                float4 hbv = hsrc[hpad(hb + j + 1)];
                fma2(a0, w1p[2 * j],     *(ull*)&ha.x);
                fma2(a1, w1p[2 * j + 1], *(ull*)&ha.z);
                fma2(a0, w1p[2 * j + 2], *(ull*)&hbv.x);
                fma2(a1, w1p[2 * j + 3], *(ull*)&hbv.z);
            }
            float acc = upksum(a0) + upksum(a1);
            acc += __shfl_xor_sync(0xffffffffu, acc, 1, 4);
            acc += __shfl_xor_sync(0xffffffffu, acc, 2, 4);
            if (q == 0) {
                float gv = acc + bB;
                sg1[lr] = (gt == 2) ? tanhf(gv) : sigm(gv);
            }
        }
        __syncthreads();
        if (tid < 32 && k < 32) {           // h0[k] (gates already transformed)
            float gi = sg0[tid];
            float gf = sg0[32 + tid];
            float gg = sg0[64 + tid];
            float go = sg0[96 + tid];
            c0 = gf * c0 + gi * gg;
            float hval = go * tanhf(c0);
            int d = (int)rank * 32 + tid;
            float* lp = ((float*)h0p[nb]) + hpad(d >> 2) * 4 + (d & 3);
            #pragma unroll
            for (unsigned r = 0; r < 4; r++) cl_store_f32(lp, r, hval);
        }
        if (tid >= 32 && tid < 64 && k >= 1) {  // h1[k-1]
            int i = tid - 32;
            float gi = sg1[i];
            float gf = sg1[32 + i];
            float gg = sg1[64 + i];
            float go = sg1[96 + i];
            c1 = gf * c1 + gi * gg;
            float hval = go * tanhf(c1);
            int d = (int)rank * 32 + i;
            float* lp = ((float*)h1p[nb]) + hpad(d >> 2) * 4 + (d & 3);
            #pragma unroll
            for (unsigned r = 0; r < 4; r++) cl_store_f32(lp, r, hval);
        }
        // light-weight cluster handoff: 64 updater threads arrive on all 4 CTAs (count=256)
        if (tid < 64) {
            #pragma unroll
            for (unsigned r = 0; r < 4; r++) mbar_arrive_remote(mbar_a, r);
        }
        mbar_wait_cluster(mbar_a, (unsigned)(k & 1));
    }

    if (rank == 0) {                       // final projection (h1[31] in h1p[1])
        float v = 0.f;
        if (tid < 128) {
            v = ((float*)h1p[1])[hpad(tid >> 2) * 4 + (tid & 3)] * Wlin[tid];
            sg0[tid] = v;
        }
        __syncthreads();
        if (tid < 32) {
            float s = sg0[tid] + sg0[tid + 32] + sg0[tid + 64] + sg0[tid + 96];
            #pragma unroll
            for (int off = 16; off; off >>= 1) s += __shfl_xor_sync(0xffffffffu, s, off);
            if (tid == 0) out[batch] = s + blin[0];
        }
    }
    cl_sync();   // no CTA exits while peers may still target its smem
}

// ---------------- launch ----------------
extern "C" void kernel_launch(void* const* d_in, const int* in_sizes, int n_in,
                              void* d_out, int out_size) {
    const float* x     = (const float*)d_in[0];
    const int*   ei    = (const int*)d_in[1];
    const float* Wl1   = (const float*)d_in[2];
    const float* attl1 = (const float*)d_in[3];
    const float* attr1 = (const float*)d_in[4];
    const float* b1    = (const float*)d_in[5];
    const float* Wl2   = (const float*)d_in[6];
    const float* attl2 = (const float*)d_in[7];
    const float* attr2 = (const float*)d_in[8];
    const float* b2    = (const float*)d_in[9];
    const float* Wih0  = (const float*)d_in[10];
    const float* Whh0  = (const float*)d_in[11];
    const float* bih0  = (const float*)d_in[12];
    const float* bhh0  = (const float*)d_in[13];
    const float* Wih1  = (const float*)d_in[14];
    const float* Whh1  = (const float*)d_in[15];
    const float* bih1  = (const float*)d_in[16];
    const float* bhh1  = (const float*)d_in[17];
    const float* Wlin  = (const float*)d_in[18];
    const float* blin  = (const float*)d_in[19];
    float* out = (float*)d_out;

    k_pass1<<<dim3(64, T_STEPS), 256>>>(ei);
    k_pass2<<<dim3(64, T_STEPS), 256>>>(ei);
    k_gat1<<<dim3(MAX_SLOTS, T_STEPS), HID>>>(x, Wl1, attl1, attr1, b1, Wl2,
                                              attl2, attr2, b2);
    k_lstm_cl<<<128, 512>>>(Wih0, Whh0, bih0, bhh0,
                            Wih1, Whh1, bih1, bhh1, Wlin, blin, out);
}

// round 10
// speedup vs baseline: 1.0003x; 1.0003x over previous
#include <cuda_runtime.h>
#include <math.h>
#include <stdint.h>

#define T_STEPS 64
#define NN 16384
#define NE 262144
#define F_IN 8
#define H1 12
#define C1 16
#define HID 192
#define CAP0 256
#define MAX_SLOTS 64
#define CAPE 4096
#define LOCAL_CAP 128

// ---------------- scratch (static device globals; zero-initialized at load) ----------------
__device__ int   g_cnt0[T_STEPS];
__device__ int   g_e0[T_STEPS][CAP0];     // raw (atomic order) from pass1
__device__ int   g_s0[T_STEPS][CAP0];
__device__ int   g_e0s[T_STEPS][CAP0];    // canonical sorted copies (written by pass2 block0)
__device__ int   g_s0s[T_STEPS][CAP0];
__device__ int   g_slot0[T_STEPS][CAP0];
__device__ int   g_n0[T_STEPS];
__device__ int   g_scnt[T_STEPS];
__device__ int   g_S[T_STEPS][MAX_SLOTS];
__device__ int   g_incnt[T_STEPS];
__device__ int   g_ie_e[T_STEPS][CAPE];
__device__ int   g_ie_src[T_STEPS][CAPE];
__device__ int   g_ie_dst[T_STEPS][CAPE];
__device__ float g_xl2[T_STEPS][MAX_SLOTS];
__device__ float g_series[T_STEPS];
__device__ int   g_done3[T_STEPS];

__device__ __forceinline__ float lrelu(float x) { return x > 0.f ? x : 0.2f * x; }
__device__ __forceinline__ float sigm(float x) { return 1.f / (1.f + expf(-x)); }

// ---- packed fp32x2 FMA (sm_103a) ----
typedef unsigned long long ull;
__device__ __forceinline__ void fma2(ull& acc, ull w, ull h) {
    asm("fma.rn.f32x2 %0, %1, %2, %0;" : "+l"(acc) : "l"(w), "l"(h));
}
__device__ __forceinline__ ull pk2(float x, float y) {
    ull r; asm("mov.b64 %0, {%1, %2};" : "=l"(r) : "f"(x), "f"(y)); return r;
}
__device__ __forceinline__ float upksum(ull a) {
    float x, y; asm("mov.b64 {%0, %1}, %2;" : "=f"(x), "=f"(y) : "l"(a)); return x + y;
}

__device__ __forceinline__ void edit_factor(int e, float& mul, float& add) {
    mul = 1.f; add = 0.f;
    if (e >= 0 && e < 23) {
        switch (e) {
            case 1: case 2: case 12: case 17: case 19: case 22: mul = 0.9f; break;
            case 7: case 14: mul = 0.9f; add = 0.1f; break;
            case 10: case 13: mul = 0.9f; add = 0.05f; break;
            default: break;
        }
    }
}

// ------------- K1: find edges with dst == 0 (16 vals/thread, min-tree) -------------
__global__ void k_pass1(const int* __restrict__ ei) {
    const int t = blockIdx.y;
    const int* __restrict__ src = ei + (size_t)t * 2 * NE;
    const int* __restrict__ dst = src + NE;
    const int e0 = blockIdx.x * (256 * 16) + threadIdx.x * 16;
    int4 v0 = *(const int4*)(dst + e0);
    int4 v1 = *(const int4*)(dst + e0 + 4);
    int4 v2 = *(const int4*)(dst + e0 + 8);
    int4 v3 = *(const int4*)(dst + e0 + 12);
    int m0 = min(min(v0.x, v0.y), min(v0.z, v0.w));
    int m1 = min(min(v1.x, v1.y), min(v1.z, v1.w));
    int m2 = min(min(v2.x, v2.y), min(v2.z, v2.w));
    int m3 = min(min(v3.x, v3.y), min(v3.z, v3.w));
    if (min(min(m0, m1), min(m2, m3)) == 0) {
        int vals[16] = { v0.x, v0.y, v0.z, v0.w, v1.x, v1.y, v1.z, v1.w,
                         v2.x, v2.y, v2.z, v2.w, v3.x, v3.y, v3.z, v3.w };
        #pragma unroll
        for (int k = 0; k < 16; k++) {
            if (vals[k] == 0) {
                int p = atomicAdd(&g_cnt0[t], 1);
                if (p < CAP0) { g_e0[t][p] = e0 + k; g_s0[t][p] = src[e0 + k]; }
            }
        }
    }
}

// -- K2: edges into frontier set (page filter + byte-map; canonical build merged in) --
__global__ void k_pass2(const int* __restrict__ ei) {
    __shared__ unsigned char bmap[NN];   // 16 KB membership byte map
    __shared__ unsigned pagef[2];        // 64-bit page filter (256-node pages)
    const int t = blockIdx.y;
    {
        int4* bm4 = (int4*)bmap;
        int4 z = make_int4(0, 0, 0, 0);
        for (int i = threadIdx.x; i < NN / 16; i += 256) bm4[i] = z;
    }
    if (threadIdx.x < 2) pagef[threadIdx.x] = 0;
    __syncthreads();
    int n = g_cnt0[t]; if (n > CAP0) n = CAP0;
    if (threadIdx.x < n) {
        int s = g_s0[t][threadIdx.x];
        bmap[s] = 1;
        unsigned pg = (unsigned)s >> 8;
        atomicOr(&pagef[pg >> 5], 1u << (pg & 31));
    }
    if (threadIdx.x == 0) {               // node 0 itself
        bmap[0] = 1;
        atomicOr(&pagef[0], 1u);
    }

    // block x==0, thread 0: build canonical sorted structures (separate arrays -> no race)
    if (blockIdx.x == 0 && threadIdx.x == 0) {
        int le[CAP0], ls[CAP0];
        for (int i = 0; i < n; i++) { le[i] = g_e0[t][i]; ls[i] = g_s0[t][i]; }
        for (int i = 1; i < n; i++) {
            int ke = le[i], ks = ls[i], j = i - 1;
            while (j >= 0 && le[j] > ke) { le[j + 1] = le[j]; ls[j + 1] = ls[j]; j--; }
            le[j + 1] = ke; ls[j + 1] = ks;
        }
        int sc = 1;
        g_S[t][0] = 0;
        for (int i = 0; i < n; i++) {
            int s = ls[i], slot = -1;
            for (int j = 0; j < sc; j++) if (g_S[t][j] == s) { slot = j; break; }
            if (slot < 0 && sc < MAX_SLOTS) { g_S[t][sc] = s; slot = sc; sc++; }
            g_slot0[t][i] = slot;
            g_e0s[t][i] = le[i]; g_s0s[t][i] = ls[i];
        }
        g_scnt[t] = sc;
        g_n0[t] = n;
    }
    __syncthreads();
    const unsigned pf0 = pagef[0], pf1 = pagef[1];

    const int* __restrict__ src = ei + (size_t)t * 2 * NE;
    const int* __restrict__ dst = src + NE;
    const int e0 = blockIdx.x * (256 * 16) + threadIdx.x * 16;
    int4 v0 = *(const int4*)(dst + e0);
    int4 v1 = *(const int4*)(dst + e0 + 4);
    int4 v2 = *(const int4*)(dst + e0 + 8);
    int4 v3 = *(const int4*)(dst + e0 + 12);
    int vals[16] = { v0.x, v0.y, v0.z, v0.w, v1.x, v1.y, v1.z, v1.w,
                     v2.x, v2.y, v2.z, v2.w, v3.x, v3.y, v3.z, v3.w };
    #pragma unroll
    for (int k = 0; k < 16; k++) {
        int d = vals[k];
        unsigned pg = (unsigned)d >> 8;
        unsigned w = (pg >= 32) ? pf1 : pf0;
        if ((w >> (pg & 31)) & 1u) {
            if (bmap[d]) {
                int p = atomicAdd(&g_incnt[t], 1);
                if (p < CAPE) { g_ie_e[t][p] = e0 + k; g_ie_src[t][p] = src[e0 + k]; g_ie_dst[t][p] = d; }
            }
        }
    }
}

// ==== K3: GAT layer 1 at frontier nodes (+ fused layer-2 in last-finishing block) ====
__global__ void k_gat1(const float* __restrict__ x, const float* __restrict__ Wl1,
                       const float* __restrict__ attl1, const float* __restrict__ attr1,
                       const float* __restrict__ b1, const float* __restrict__ Wl2,
                       const float* __restrict__ attl2, const float* __restrict__ attr2,
                       const float* __restrict__ b2) {
    int t = blockIdx.y;
    int slot = blockIdx.x;
    int tid = threadIdx.x;              // 192 threads

    __shared__ float sWl[F_IN * HID];
    __shared__ float sAl[HID], sAr[HID], sB[HID], sW2[HID];
    __shared__ int   se[LOCAL_CAP], ss[LOCAL_CAP];
    __shared__ float sxr[LOCAL_CAP][F_IN];
    __shared__ float sal[LOCAL_CAP][H1];
    __shared__ float sm_[H1], sden[H1], sarU[H1];
    __shared__ float sfmul[LOCAL_CAP], sfadd[LOCAL_CAP];
    __shared__ float sred[HID];
    __shared__ int   sdeg;
    __shared__ int   sLast;
    __shared__ float l2xs[CAP0 + 1], l2a[CAP0 + 1];

    const int active = (slot < g_scnt[t]);
    if (active) {
        int u = g_S[t][slot];
        int h = tid >> 4, c = tid & 15;

        for (int i = tid; i < F_IN * HID; i += HID) sWl[i] = Wl1[i];
        sAl[tid] = attl1[tid]; sAr[tid] = attr1[tid]; sB[tid] = b1[tid]; sW2[tid] = Wl2[tid];
        if (tid == 0) sdeg = 0;
        __syncthreads();

        int cnt = g_incnt[t]; if (cnt > CAPE) cnt = CAPE;
        for (int i = tid; i < cnt; i += HID) {
            if (g_ie_dst[t][i] == u) {
                int p = atomicAdd(&sdeg, 1);
                if (p < LOCAL_CAP - 1) { se[p] = g_ie_e[t][i]; ss[p] = g_ie_src[t][i]; }
            }
        }
        __syncthreads();
        int deg = sdeg; if (deg > LOCAL_CAP - 1) deg = LOCAL_CAP - 1;
        if (tid == 0) {
            for (int i = 1; i < deg; i++) {                 // canonical order
                int ke = se[i], ks = ss[i], j = i - 1;
                while (j >= 0 && se[j] > ke) { se[j + 1] = se[j]; ss[j + 1] = ss[j]; j--; }
                se[j + 1] = ke; ss[j + 1] = ks;
            }
            se[deg] = 0x7fffffff; ss[deg] = u;              // self-loop last (never edited)
        }
        __syncthreads();
        int ndeg = deg + 1;

        for (int i = tid; i < ndeg * F_IN; i += HID)
            sxr[i >> 3][i & 7] = x[((size_t)t * NN + ss[i >> 3]) * F_IN + (i & 7)];
        __syncthreads();

        {   // ar_u from xl1[u] (self row at index deg)
            float v = 0.f;
            #pragma unroll
            for (int k = 0; k < F_IN; k++) v += sxr[deg][k] * sWl[k * HID + tid];
            float r = v * sAr[tid];
            #pragma unroll
            for (int off = 8; off; off >>= 1) r += __shfl_xor_sync(0xffffffffu, r, off, 16);
            if (c == 0) sarU[h] = r;
        }
        for (int i = 0; i < ndeg; i++) {
            float v = 0.f;
            #pragma unroll
            for (int k = 0; k < F_IN; k++) v += sxr[i][k] * sWl[k * HID + tid];
            float a = v * sAl[tid];
            #pragma unroll
            for (int off = 8; off; off >>= 1) a += __shfl_xor_sync(0xffffffffu, a, off, 16);
            if (c == 0) sal[i][h] = a;
        }
        __syncthreads();

        if (tid < H1) {
            int hh = tid;
            float m = -1e30f;
            for (int i = 0; i < ndeg; i++) { float a = lrelu(sal[i][hh] + sarU[hh]); if (a > m) m = a; }
            float den = 0.f;
            for (int i = 0; i < ndeg; i++) den += expf(lrelu(sal[i][hh] + sarU[hh]) - m);
            sm_[hh] = m; sden[hh] = den + 1e-16f;
        }
        if (tid >= 32 && tid < 32 + ndeg) {
            int i = tid - 32; float mu, ad; edit_factor(se[i], mu, ad); sfmul[i] = mu; sfadd[i] = ad;
        }
        __syncthreads();

        float acc = 0.f;
        for (int i = 0; i < ndeg; i++) {
            float a = lrelu(sal[i][h] + sarU[h]);
            float alpha = expf(a - sm_[h]) / sden[h];
            alpha = sfmul[i] * alpha + sfadd[i];
            float v = 0.f;
            #pragma unroll
            for (int k = 0; k < F_IN; k++) v += sxr[i][k] * sWl[k * HID + tid];
            acc += alpha * v;
        }
        acc += sB[tid];
        float e1 = acc > 0.f ? acc : (expf(acc) - 1.f);      // ELU
        sred[tid] = e1 * sW2[tid];
        __syncthreads();
        if (tid < 64) sred[tid] = sred[tid] + sred[tid + 64] + sred[tid + 128];
        __syncthreads();
        if (tid < 32) {
            float v = sred[tid] + sred[tid + 32];
            #pragma unroll
            for (int off = 16; off; off >>= 1) v += __shfl_xor_sync(0xffffffffu, v, off);
            if (tid == 0) g_xl2[t][slot] = v;
        }
    }

    // -------- completion counter; last block of this t runs GAT layer 2 --------
    __syncthreads();
    if (tid == 0) {
        __threadfence();
        int old = atomicAdd(&g_done3[t], 1);
        sLast = (old == gridDim.x - 1) ? 1 : 0;
        if (sLast) __threadfence();
    }
    __syncthreads();
    if (sLast) {
        int n = g_n0[t];
        if (tid < 32) {
            float al2 = attl2[0], ar2v = attr2[0];
            float x0 = *(volatile float*)&g_xl2[t][0];
            float ar0 = x0 * ar2v;
            float m = -1e30f;
            for (int i = tid; i <= n; i += 32) {
                float xs = (i < n) ? *(volatile float*)&g_xl2[t][g_slot0[t][i]] : x0;
                float a = lrelu(xs * al2 + ar0);
                l2xs[i] = xs; l2a[i] = a;
                m = fmaxf(m, a);
            }
            __syncwarp();
            #pragma unroll
            for (int off = 16; off; off >>= 1) m = fmaxf(m, __shfl_xor_sync(0xffffffffu, m, off));
            float den = 0.f;
            for (int i = tid; i <= n; i += 32) den += expf(l2a[i] - m);
            #pragma unroll
            for (int off = 16; off; off >>= 1) den += __shfl_xor_sync(0xffffffffu, den, off);
            den += 1e-16f;
            float outv = 0.f;
            for (int i = tid; i <= n; i += 32) {
                float alpha = expf(l2a[i] - m) / den;
                int e = (i < n) ? g_e0s[t][i] : 0x7fffffff;
                float mu, ad; edit_factor(e, mu, ad);
                outv += (mu * alpha + ad) * l2xs[i];
            }
            #pragma unroll
            for (int off = 16; off; off >>= 1) outv += __shfl_xor_sync(0xffffffffu, outv, off);
            if (tid == 0) {
                g_series[t] = outv + b2[0];
                // reset per-t state for next graph replay
                g_cnt0[t] = 0; g_incnt[t] = 0; g_done3[t] = 0;
            }
        }
    }
}

// ========= K4: cluster-4 LSTM, reg weights, mbarrier sync, producer nonlinearities =========
__device__ __forceinline__ int hpad(int k4) { return k4 + (k4 >> 3); }
__device__ __forceinline__ unsigned cl_rank() {
    unsigned r; asm("mov.u32 %0, %%cluster_ctarank;" : "=r"(r)); return r;
}
__device__ __forceinline__ void cl_sync() {
    asm volatile("barrier.cluster.arrive.aligned;\n\tbarrier.cluster.wait.aligned;" ::: "memory");
}
__device__ __forceinline__ void cl_store_f32(float* p, unsigned rank, float v) {
    uint32_t a = (uint32_t)__cvta_generic_to_shared(p);
    uint32_t pa;
    asm("mapa.shared::cluster.u32 %0, %1, %2;" : "=r"(pa) : "r"(a), "r"(rank));
    asm volatile("st.shared::cluster.f32 [%0], %1;" :: "r"(pa), "f"(v) : "memory");
}
__device__ __forceinline__ void mbar_arrive_remote(uint32_t mbar, unsigned rank) {
    uint32_t rem;
    asm("mapa.shared::cluster.u32 %0, %1, %2;" : "=r"(rem) : "r"(mbar), "r"(rank));
    asm volatile("mbarrier.arrive.release.cluster.shared::cluster.b64 _, [%0];"
                 :: "r"(rem) : "memory");
}
__device__ __forceinline__ void mbar_wait_cluster(uint32_t mbar, unsigned parity) {
    asm volatile(
        "{\n\t"
        ".reg .pred P1;\n\t"
        "WL_%=:\n\t"
        "mbarrier.try_wait.parity.acquire.cluster.shared::cta.b64 P1, [%0], %1, 0x989680;\n\t"
        "@P1 bra.uni WD_%=;\n\t"
        "bra.uni WL_%=;\n\t"
        "WD_%=:\n\t"
        "}"
        :: "r"(mbar), "r"(parity) : "memory");
}

__global__ void __cluster_dims__(4, 1, 1) __launch_bounds__(512, 1)
k_lstm_cl(const float* __restrict__ Wih0, const float* __restrict__ Whh0,
          const float* __restrict__ bih0, const float* __restrict__ bhh0,
          const float* __restrict__ Wih1, const float* __restrict__ Whh1,
          const float* __restrict__ bih1, const float* __restrict__ bhh1,
          const float* __restrict__ Wlin, const float* __restrict__ blin,
          float* __restrict__ out) {
    __shared__ __align__(16) float4 h0p[2][36];
    __shared__ __align__(16) float4 h1p[2][36];
    __shared__ float sg0[128], sg1[128];
    __shared__ float xs[32];
    __shared__ __align__(8) unsigned long long mbar;

    const unsigned rank = cl_rank();
    const int batch = blockIdx.x >> 2;
    const int tid = threadIdx.x;
    const int lr = tid >> 2, q = tid & 3;            // row 0..127, k-quarter
    const int gt = lr >> 5, dl = lr & 31;
    const int gr = gt * 128 + (int)rank * 32 + dl;   // global gate row
    const uint32_t mbar_a = (uint32_t)__cvta_generic_to_shared(&mbar);

    ull w0p[16], w1p[32];
    {
        const float4* W0 = (const float4*)(Whh0 + (size_t)gr * 128) + 8 * q;
        #pragma unroll
        for (int j = 0; j < 8; j++) {
            float4 w = W0[j];
            w0p[2 * j] = pk2(w.x, w.y); w0p[2 * j + 1] = pk2(w.z, w.w);
        }
        const float* Wsrc = (q < 2) ? Wih1 : Whh1;
        const float4* W1 = (const float4*)(Wsrc + (size_t)gr * 128) + 16 * (q & 1);
        #pragma unroll
        for (int j = 0; j < 16; j++) {
            float4 w = W1[j];
            w1p[2 * j] = pk2(w.x, w.y); w1p[2 * j + 1] = pk2(w.z, w.w);
        }
    }
    float wih0v = 0.f, bA = 0.f, bB = 0.f;
    if (q == 0) { wih0v = Wih0[gr]; bA = bih0[gr] + bhh0[gr]; bB = bih1[gr] + bhh1[gr]; }
    if (tid < 32) xs[tid] = g_series[batch + tid];
    {
        float* hz = (float*)&h0p[0][0];
        for (int i = tid; i < 2 * 2 * 36 * 4; i += 512) hz[i] = 0.f;
    }
    if (tid == 0) {
        asm volatile("mbarrier.init.shared.b64 [%0], %1;" :: "r"(mbar_a), "r"(256u) : "memory");
    }
    float c0 = 0.f, c1 = 0.f;
    const int hb = 16 * (q & 1);
    cl_sync();   // one full cluster barrier: mbarrier init + zeroed h visible everywhere

    for (int k = 0; k <= 32; k++) {
        const int pb = k & 1, nb = pb ^ 1;
        if (k < 32) {                     // gates0 for step k (reads h0[k-1])
            const float4* hv = h0p[pb];
            ull a0 = 0ull, a1 = 0ull;
            #pragma unroll
            for (int j = 0; j < 8; j += 2) {
                float4 ha = hv[hpad(8 * q + j)];
                float4 hbv = hv[hpad(8 * q + j + 1)];
                fma2(a0, w0p[2 * j],     *(ull*)&ha.x);
                fma2(a1, w0p[2 * j + 1], *(ull*)&ha.z);
                fma2(a0, w0p[2 * j + 2], *(ull*)&hbv.x);
                fma2(a1, w0p[2 * j + 3], *(ull*)&hbv.z);
            }
            float acc = upksum(a0) + upksum(a1);
            acc += __shfl_xor_sync(0xffffffffu, acc, 1, 4);
            acc += __shfl_xor_sync(0xffffffffu, acc, 2, 4);
            if (q == 0) {
                float gv = acc + bA + wih0v * xs[k];
                sg0[lr] = (gt == 2) ? tanhf(gv) : sigm(gv);   // producer-side nonlinearity
            }
        }
        if (k >= 1) {                     // gates1 for step k-1 (reads h0[k-1], h1[k-2])
            const float4* hsrc = (q < 2) ? h0p[pb] : h1p[pb];
            ull a0 = 0ull, a1 = 0ull;
            #pragma unroll
            for (int j = 0; j < 16; j += 2) {
                float4 ha = hsrc[hpad(hb + j)];
                float4 hbv = hsrc[hpad(hb + j + 1)];
                fma2(a0, w1p[2 * j],     *(ull*)&ha.x);
                fma2(a1, w1p[2 * j + 1], *(ull*)&ha.z);
                fma2(a0, w1p[2 * j + 2], *(ull*)&hbv.x);
                fma2(a1, w1p[2 * j + 3], *(ull*)&hbv.z);
            }
            float acc = upksum(a0) + upksum(a1);
            acc += __shfl_xor_sync(0xffffffffu, acc, 1, 4);
            acc += __shfl_xor_sync(0xffffffffu, acc, 2, 4);
            if (q == 0) {
                float gv = acc + bB;
                sg1[lr] = (gt == 2) ? tanhf(gv) : sigm(gv);
            }
        }
        __syncthreads();
        if (tid < 32 && k < 32) {           // h0[k] (gates already transformed)
            float gi = sg0[tid];
            float gf = sg0[32 + tid];
            float gg = sg0[64 + tid];
            float go = sg0[96 + tid];
            c0 = gf * c0 + gi * gg;
            float hval = go * tanhf(c0);
            int d = (int)rank * 32 + tid;
            float* lp = ((float*)h0p[nb]) + hpad(d >> 2) * 4 + (d & 3);
            #pragma unroll
            for (unsigned r = 0; r < 4; r++) cl_store_f32(lp, r, hval);
        }
        if (tid >= 32 && tid < 64 && k >= 1) {  // h1[k-1]
            int i = tid - 32;
            float gi = sg1[i];
            float gf = sg1[32 + i];
            float gg = sg1[64 + i];
            float go = sg1[96 + i];
            c1 = gf * c1 + gi * gg;
            float hval = go * tanhf(c1);
            int d = (int)rank * 32 + i;
            float* lp = ((float*)h1p[nb]) + hpad(d >> 2) * 4 + (d & 3);
            #pragma unroll
            for (unsigned r = 0; r < 4; r++) cl_store_f32(lp, r, hval);
        }
        // light-weight cluster handoff: 64 updater threads arrive on all 4 CTAs (count=256)
        if (tid < 64) {
            #pragma unroll
            for (unsigned r = 0; r < 4; r++) mbar_arrive_remote(mbar_a, r);
        }
        mbar_wait_cluster(mbar_a, (unsigned)(k & 1));
    }

    if (rank == 0) {                       // final projection (h1[31] in h1p[1])
        float v = 0.f;
        if (tid < 128) {
            v = ((float*)h1p[1])[hpad(tid >> 2) * 4 + (tid & 3)] * Wlin[tid];
            sg0[tid] = v;
        }
        __syncthreads();
        if (tid < 32) {
            float s = sg0[tid] + sg0[tid + 32] + sg0[tid + 64] + sg0[tid + 96];
            #pragma unroll
            for (int off = 16; off; off >>= 1) s += __shfl_xor_sync(0xffffffffu, s, off);
            if (tid == 0) out[batch] = s + blin[0];
        }
    }
    cl_sync();   // no CTA exits while peers may still target its smem
}

// ---------------- launch ----------------
extern "C" void kernel_launch(void* const* d_in, const int* in_sizes, int n_in,
                              void* d_out, int out_size) {
    const float* x     = (const float*)d_in[0];
    const int*   ei    = (const int*)d_in[1];
    const float* Wl1   = (const float*)d_in[2];
    const float* attl1 = (const float*)d_in[3];
    const float* attr1 = (const float*)d_in[4];
    const float* b1    = (const float*)d_in[5];
    const float* Wl2   = (const float*)d_in[6];
    const float* attl2 = (const float*)d_in[7];
    const float* attr2 = (const float*)d_in[8];
    const float* b2    = (const float*)d_in[9];
    const float* Wih0  = (const float*)d_in[10];
    const float* Whh0  = (const float*)d_in[11];
    const float* bih0  = (const float*)d_in[12];
    const float* bhh0  = (const float*)d_in[13];
    const float* Wih1  = (const float*)d_in[14];
    const float* Whh1  = (const float*)d_in[15];
    const float* bih1  = (const float*)d_in[16];
    const float* bhh1  = (const float*)d_in[17];
    const float* Wlin  = (const float*)d_in[18];
    const float* blin  = (const float*)d_in[19];
    float* out = (float*)d_out;

    k_pass1<<<dim3(64, T_STEPS), 256>>>(ei);
    k_pass2<<<dim3(64, T_STEPS), 256>>>(ei);
    k_gat1<<<dim3(MAX_SLOTS, T_STEPS), HID>>>(x, Wl1, attl1, attr1, b1, Wl2,
                                              attl2, attr2, b2);
    k_lstm_cl<<<128, 512>>>(Wih0, Whh0, bih0, bhh0,
                            Wih1, Whh1, bih1, bhh1, Wlin, blin, out);
}

// round 11
// speedup vs baseline: 1.0010x; 1.0007x over previous
#include <cuda_runtime.h>
#include <math.h>
#include <stdint.h>

#define T_STEPS 64
#define NN 16384
#define NE 262144
#define F_IN 8
#define H1 12
#define C1 16
#define HID 192
#define CAP0 256
#define MAX_SLOTS 64
#define CAPE 4096
#define LOCAL_CAP 128

// ---------------- scratch (static device globals; zero-initialized at load) ----------------
__device__ int   g_cnt0[T_STEPS];
__device__ int   g_e0[T_STEPS][CAP0];     // raw (atomic order) from pass1
__device__ int   g_s0[T_STEPS][CAP0];
__device__ int   g_e0s[T_STEPS][CAP0];    // canonical sorted copies (written by pass2 block0)
__device__ int   g_s0s[T_STEPS][CAP0];
__device__ int   g_slot0[T_STEPS][CAP0];
__device__ int   g_n0[T_STEPS];
__device__ int   g_scnt[T_STEPS];
__device__ int   g_S[T_STEPS][MAX_SLOTS];
__device__ int   g_incnt[T_STEPS];
__device__ int   g_ie_e[T_STEPS][CAPE];
__device__ int   g_ie_src[T_STEPS][CAPE];
__device__ int   g_ie_dst[T_STEPS][CAPE];
__device__ float g_xl2[T_STEPS][MAX_SLOTS];
__device__ float g_series[T_STEPS];
__device__ int   g_done3[T_STEPS];

__device__ __forceinline__ float lrelu(float x) { return x > 0.f ? x : 0.2f * x; }
__device__ __forceinline__ float sigm(float x) { return 1.f / (1.f + expf(-x)); }

// ---- packed fp32x2 FMA (sm_103a) ----
typedef unsigned long long ull;
__device__ __forceinline__ void fma2(ull& acc, ull w, ull h) {
    asm("fma.rn.f32x2 %0, %1, %2, %0;" : "+l"(acc) : "l"(w), "l"(h));
}
__device__ __forceinline__ ull pk2(float x, float y) {
    ull r; asm("mov.b64 %0, {%1, %2};" : "=l"(r) : "f"(x), "f"(y)); return r;
}
__device__ __forceinline__ float upksum(ull a) {
    float x, y; asm("mov.b64 {%0, %1}, %2;" : "=f"(x), "=f"(y) : "l"(a)); return x + y;
}

__device__ __forceinline__ void edit_factor(int e, float& mul, float& add) {
    mul = 1.f; add = 0.f;
    if (e >= 0 && e < 23) {
        switch (e) {
            case 1: case 2: case 12: case 17: case 19: case 22: mul = 0.9f; break;
            case 7: case 14: mul = 0.9f; add = 0.1f; break;
            case 10: case 13: mul = 0.9f; add = 0.05f; break;
            default: break;
        }
    }
}

// ------------- K1: find edges with dst == 0 (16 vals/thread, min-tree) -------------
__global__ void k_pass1(const int* __restrict__ ei) {
    const int t = blockIdx.y;
    const int* __restrict__ src = ei + (size_t)t * 2 * NE;
    const int* __restrict__ dst = src + NE;
    const int e0 = blockIdx.x * (256 * 16) + threadIdx.x * 16;
    int4 v0 = *(const int4*)(dst + e0);
    int4 v1 = *(const int4*)(dst + e0 + 4);
    int4 v2 = *(const int4*)(dst + e0 + 8);
    int4 v3 = *(const int4*)(dst + e0 + 12);
    int m0 = min(min(v0.x, v0.y), min(v0.z, v0.w));
    int m1 = min(min(v1.x, v1.y), min(v1.z, v1.w));
    int m2 = min(min(v2.x, v2.y), min(v2.z, v2.w));
    int m3 = min(min(v3.x, v3.y), min(v3.z, v3.w));
    if (min(min(m0, m1), min(m2, m3)) == 0) {
        int vals[16] = { v0.x, v0.y, v0.z, v0.w, v1.x, v1.y, v1.z, v1.w,
                         v2.x, v2.y, v2.z, v2.w, v3.x, v3.y, v3.z, v3.w };
        #pragma unroll
        for (int k = 0; k < 16; k++) {
            if (vals[k] == 0) {
                int p = atomicAdd(&g_cnt0[t], 1);
                if (p < CAP0) { g_e0[t][p] = e0 + k; g_s0[t][p] = src[e0 + k]; }
            }
        }
    }
}

// -- K2: edges into frontier set (page filter + byte-map; canonical build merged in) --
__global__ void k_pass2(const int* __restrict__ ei) {
    __shared__ unsigned char bmap[NN];   // 16 KB membership byte map
    __shared__ unsigned pagef[2];        // 64-bit page filter (256-node pages)
    const int t = blockIdx.y;
    {
        int4* bm4 = (int4*)bmap;
        int4 z = make_int4(0, 0, 0, 0);
        for (int i = threadIdx.x; i < NN / 16; i += 256) bm4[i] = z;
    }
    if (threadIdx.x < 2) pagef[threadIdx.x] = 0;
    __syncthreads();
    int n = g_cnt0[t]; if (n > CAP0) n = CAP0;
    if (threadIdx.x < n) {
        int s = g_s0[t][threadIdx.x];
        bmap[s] = 1;
        unsigned pg = (unsigned)s >> 8;
        atomicOr(&pagef[pg >> 5], 1u << (pg & 31));
    }
    if (threadIdx.x == 0) {               // node 0 itself
        bmap[0] = 1;
        atomicOr(&pagef[0], 1u);
    }

    // block x==0, thread 0: build canonical sorted structures (separate arrays -> no race)
    if (blockIdx.x == 0 && threadIdx.x == 0) {
        int le[CAP0], ls[CAP0];
        for (int i = 0; i < n; i++) { le[i] = g_e0[t][i]; ls[i] = g_s0[t][i]; }
        for (int i = 1; i < n; i++) {
            int ke = le[i], ks = ls[i], j = i - 1;
            while (j >= 0 && le[j] > ke) { le[j + 1] = le[j]; ls[j + 1] = ls[j]; j--; }
            le[j + 1] = ke; ls[j + 1] = ks;
        }
        int sc = 1;
        g_S[t][0] = 0;
        for (int i = 0; i < n; i++) {
            int s = ls[i], slot = -1;
            for (int j = 0; j < sc; j++) if (g_S[t][j] == s) { slot = j; break; }
            if (slot < 0 && sc < MAX_SLOTS) { g_S[t][sc] = s; slot = sc; sc++; }
            g_slot0[t][i] = slot;
            g_e0s[t][i] = le[i]; g_s0s[t][i] = ls[i];
        }
        g_scnt[t] = sc;
        g_n0[t] = n;
    }
    __syncthreads();
    const unsigned pf0 = pagef[0], pf1 = pagef[1];

    const int* __restrict__ src = ei + (size_t)t * 2 * NE;
    const int* __restrict__ dst = src + NE;
    const int e0 = blockIdx.x * (256 * 16) + threadIdx.x * 16;
    int4 v0 = *(const int4*)(dst + e0);
    int4 v1 = *(const int4*)(dst + e0 + 4);
    int4 v2 = *(const int4*)(dst + e0 + 8);
    int4 v3 = *(const int4*)(dst + e0 + 12);
    int vals[16] = { v0.x, v0.y, v0.z, v0.w, v1.x, v1.y, v1.z, v1.w,
                     v2.x, v2.y, v2.z, v2.w, v3.x, v3.y, v3.z, v3.w };
    #pragma unroll
    for (int k = 0; k < 16; k++) {
        int d = vals[k];
        unsigned pg = (unsigned)d >> 8;
        unsigned w = (pg >= 32) ? pf1 : pf0;
        if ((w >> (pg & 31)) & 1u) {
            if (bmap[d]) {
                int p = atomicAdd(&g_incnt[t], 1);
                if (p < CAPE) { g_ie_e[t][p] = e0 + k; g_ie_src[t][p] = src[e0 + k]; g_ie_dst[t][p] = d; }
            }
        }
    }
}

// ==== K3: GAT layer 1 at frontier nodes (+ fused layer-2 in last-finishing block) ====
__global__ void k_gat1(const float* __restrict__ x, const float* __restrict__ Wl1,
                       const float* __restrict__ attl1, const float* __restrict__ attr1,
                       const float* __restrict__ b1, const float* __restrict__ Wl2,
                       const float* __restrict__ attl2, const float* __restrict__ attr2,
                       const float* __restrict__ b2) {
    int t = blockIdx.y;
    int slot = blockIdx.x;
    int tid = threadIdx.x;              // 192 threads

    __shared__ float sWl[F_IN * HID];
    __shared__ float sAl[HID], sAr[HID], sB[HID], sW2[HID];
    __shared__ int   se[LOCAL_CAP], ss[LOCAL_CAP];
    __shared__ float sxr[LOCAL_CAP][F_IN];
    __shared__ float sal[LOCAL_CAP][H1];
    __shared__ float sm_[H1], sden[H1], sarU[H1];
    __shared__ float sfmul[LOCAL_CAP], sfadd[LOCAL_CAP];
    __shared__ float sred[HID];
    __shared__ int   sdeg;
    __shared__ int   sLast;
    __shared__ float l2xs[CAP0 + 1], l2a[CAP0 + 1];

    const int active = (slot < g_scnt[t]);
    if (active) {
        int u = g_S[t][slot];
        int h = tid >> 4, c = tid & 15;

        for (int i = tid; i < F_IN * HID; i += HID) sWl[i] = Wl1[i];
        sAl[tid] = attl1[tid]; sAr[tid] = attr1[tid]; sB[tid] = b1[tid]; sW2[tid] = Wl2[tid];
        if (tid == 0) sdeg = 0;
        __syncthreads();

        int cnt = g_incnt[t]; if (cnt > CAPE) cnt = CAPE;
        for (int i = tid; i < cnt; i += HID) {
            if (g_ie_dst[t][i] == u) {
                int p = atomicAdd(&sdeg, 1);
                if (p < LOCAL_CAP - 1) { se[p] = g_ie_e[t][i]; ss[p] = g_ie_src[t][i]; }
            }
        }
        __syncthreads();
        int deg = sdeg; if (deg > LOCAL_CAP - 1) deg = LOCAL_CAP - 1;
        if (tid == 0) {
            for (int i = 1; i < deg; i++) {                 // canonical order
                int ke = se[i], ks = ss[i], j = i - 1;
                while (j >= 0 && se[j] > ke) { se[j + 1] = se[j]; ss[j + 1] = ss[j]; j--; }
                se[j + 1] = ke; ss[j + 1] = ks;
            }
            se[deg] = 0x7fffffff; ss[deg] = u;              // self-loop last (never edited)
        }
        __syncthreads();
        int ndeg = deg + 1;

        for (int i = tid; i < ndeg * F_IN; i += HID)
            sxr[i >> 3][i & 7] = x[((size_t)t * NN + ss[i >> 3]) * F_IN + (i & 7)];
        __syncthreads();

        {   // ar_u from xl1[u] (self row at index deg)
            float v = 0.f;
            #pragma unroll
            for (int k = 0; k < F_IN; k++) v += sxr[deg][k] * sWl[k * HID + tid];
            float r = v * sAr[tid];
            #pragma unroll
            for (int off = 8; off; off >>= 1) r += __shfl_xor_sync(0xffffffffu, r, off, 16);
            if (c == 0) sarU[h] = r;
        }
        for (int i = 0; i < ndeg; i++) {
            float v = 0.f;
            #pragma unroll
            for (int k = 0; k < F_IN; k++) v += sxr[i][k] * sWl[k * HID + tid];
            float a = v * sAl[tid];
            #pragma unroll
            for (int off = 8; off; off >>= 1) a += __shfl_xor_sync(0xffffffffu, a, off, 16);
            if (c == 0) sal[i][h] = a;
        }
        __syncthreads();

        if (tid < H1) {
            int hh = tid;
            float m = -1e30f;
            for (int i = 0; i < ndeg; i++) { float a = lrelu(sal[i][hh] + sarU[hh]); if (a > m) m = a; }
            float den = 0.f;
            for (int i = 0; i < ndeg; i++) den += expf(lrelu(sal[i][hh] + sarU[hh]) - m);
            sm_[hh] = m; sden[hh] = den + 1e-16f;
        }
        if (tid >= 32 && tid < 32 + ndeg) {
            int i = tid - 32; float mu, ad; edit_factor(se[i], mu, ad); sfmul[i] = mu; sfadd[i] = ad;
        }
        __syncthreads();

        float acc = 0.f;
        for (int i = 0; i < ndeg; i++) {
            float a = lrelu(sal[i][h] + sarU[h]);
            float alpha = expf(a - sm_[h]) / sden[h];
            alpha = sfmul[i] * alpha + sfadd[i];
            float v = 0.f;
            #pragma unroll
            for (int k = 0; k < F_IN; k++) v += sxr[i][k] * sWl[k * HID + tid];
            acc += alpha * v;
        }
        acc += sB[tid];
        float e1 = acc > 0.f ? acc : (expf(acc) - 1.f);      // ELU
        sred[tid] = e1 * sW2[tid];
        __syncthreads();
        if (tid < 64) sred[tid] = sred[tid] + sred[tid + 64] + sred[tid + 128];
        __syncthreads();
        if (tid < 32) {
            float v = sred[tid] + sred[tid + 32];
            #pragma unroll
            for (int off = 16; off; off >>= 1) v += __shfl_xor_sync(0xffffffffu, v, off);
            if (tid == 0) g_xl2[t][slot] = v;
        }
    }

    // -------- completion counter; last block of this t runs GAT layer 2 --------
    __syncthreads();
    if (tid == 0) {
        __threadfence();
        int old = atomicAdd(&g_done3[t], 1);
        sLast = (old == gridDim.x - 1) ? 1 : 0;
        if (sLast) __threadfence();
    }
    __syncthreads();
    if (sLast) {
        int n = g_n0[t];
        if (tid < 32) {
            float al2 = attl2[0], ar2v = attr2[0];
            float x0 = *(volatile float*)&g_xl2[t][0];
            float ar0 = x0 * ar2v;
            float m = -1e30f;
            for (int i = tid; i <= n; i += 32) {
                float xs = (i < n) ? *(volatile float*)&g_xl2[t][g_slot0[t][i]] : x0;
                float a = lrelu(xs * al2 + ar0);
                l2xs[i] = xs; l2a[i] = a;
                m = fmaxf(m, a);
            }
            __syncwarp();
            #pragma unroll
            for (int off = 16; off; off >>= 1) m = fmaxf(m, __shfl_xor_sync(0xffffffffu, m, off));
            float den = 0.f;
            for (int i = tid; i <= n; i += 32) den += expf(l2a[i] - m);
            #pragma unroll
            for (int off = 16; off; off >>= 1) den += __shfl_xor_sync(0xffffffffu, den, off);
            den += 1e-16f;
            float outv = 0.f;
            for (int i = tid; i <= n; i += 32) {
                float alpha = expf(l2a[i] - m) / den;
                int e = (i < n) ? g_e0s[t][i] : 0x7fffffff;
                float mu, ad; edit_factor(e, mu, ad);
                outv += (mu * alpha + ad) * l2xs[i];
            }
            #pragma unroll
            for (int off = 16; off; off >>= 1) outv += __shfl_xor_sync(0xffffffffu, outv, off);
            if (tid == 0) {
                g_series[t] = outv + b2[0];
                // reset per-t state for next graph replay
                g_cnt0[t] = 0; g_incnt[t] = 0; g_done3[t] = 0;
            }
        }
    }
}

// ========= K4: cluster-4 LSTM, reg weights, mbarrier sync, producer nonlinearities =========
__device__ __forceinline__ int hpad(int k4) { return k4 + (k4 >> 3); }
__device__ __forceinline__ unsigned cl_rank() {
    unsigned r; asm("mov.u32 %0, %%cluster_ctarank;" : "=r"(r)); return r;
}
__device__ __forceinline__ void cl_sync() {
    asm volatile("barrier.cluster.arrive.aligned;\n\tbarrier.cluster.wait.aligned;" ::: "memory");
}
__device__ __forceinline__ void cl_store_f32(float* p, unsigned rank, float v) {
    uint32_t a = (uint32_t)__cvta_generic_to_shared(p);
    uint32_t pa;
    asm("mapa.shared::cluster.u32 %0, %1, %2;" : "=r"(pa) : "r"(a), "r"(rank));
    asm volatile("st.shared::cluster.f32 [%0], %1;" :: "r"(pa), "f"(v) : "memory");
}
__device__ __forceinline__ void mbar_arrive_remote(uint32_t mbar, unsigned rank) {
    uint32_t rem;
    asm("mapa.shared::cluster.u32 %0, %1, %2;" : "=r"(rem) : "r"(mbar), "r"(rank));
    asm volatile("mbarrier.arrive.release.cluster.shared::cluster.b64 _, [%0];"
                 :: "r"(rem) : "memory");
}
__device__ __forceinline__ void mbar_wait_cluster(uint32_t mbar, unsigned parity) {
    asm volatile(
        "{\n\t"
        ".reg .pred P1;\n\t"
        "WL_%=:\n\t"
        "mbarrier.try_wait.parity.acquire.cluster.shared::cta.b64 P1, [%0], %1, 0x989680;\n\t"
        "@P1 bra.uni WD_%=;\n\t"
        "bra.uni WL_%=;\n\t"
        "WD_%=:\n\t"
        "}"
        :: "r"(mbar), "r"(parity) : "memory");
}

__global__ void __cluster_dims__(4, 1, 1) __launch_bounds__(512, 1)
k_lstm_cl(const float* __restrict__ Wih0, const float* __restrict__ Whh0,
          const float* __restrict__ bih0, const float* __restrict__ bhh0,
          const float* __restrict__ Wih1, const float* __restrict__ Whh1,
          const float* __restrict__ bih1, const float* __restrict__ bhh1,
          const float* __restrict__ Wlin, const float* __restrict__ blin,
          float* __restrict__ out) {
    __shared__ __align__(16) float4 h0p[2][36];
    __shared__ __align__(16) float4 h1p[2][36];
    __shared__ float sg0[128], sg1[128];
    __shared__ float xs[32];
    __shared__ __align__(8) unsigned long long mbar;

    const unsigned rank = cl_rank();
    const int batch = blockIdx.x >> 2;
    const int tid = threadIdx.x;
    const int lr = tid >> 2, q = tid & 3;            // row 0..127, k-quarter
    const int gt = lr >> 5, dl = lr & 31;
    const int gr = gt * 128 + (int)rank * 32 + dl;   // global gate row
    const uint32_t mbar_a = (uint32_t)__cvta_generic_to_shared(&mbar);

    ull w0p[16], w1p[32];
    {
        const float4* W0 = (const float4*)(Whh0 + (size_t)gr * 128) + 8 * q;
        #pragma unroll
        for (int j = 0; j < 8; j++) {
            float4 w = W0[j];
            w0p[2 * j] = pk2(w.x, w.y); w0p[2 * j + 1] = pk2(w.z, w.w);
        }
        const float* Wsrc = (q < 2) ? Wih1 : Whh1;
        const float4* W1 = (const float4*)(Wsrc + (size_t)gr * 128) + 16 * (q & 1);
        #pragma unroll
        for (int j = 0; j < 16; j++) {
            float4 w = W1[j];
            w1p[2 * j] = pk2(w.x, w.y); w1p[2 * j + 1] = pk2(w.z, w.w);
        }
    }
    float wih0v = 0.f, bA = 0.f, bB = 0.f;
    if (q == 0) { wih0v = Wih0[gr]; bA = bih0[gr] + bhh0[gr]; bB = bih1[gr] + bhh1[gr]; }
    if (tid < 32) xs[tid] = g_series[batch + tid];
    {
        float* hz = (float*)&h0p[0][0];
        for (int i = tid; i < 2 * 2 * 36 * 4; i += 512) hz[i] = 0.f;
    }
    if (tid == 0) {
        asm volatile("mbarrier.init.shared.b64 [%0], %1;" :: "r"(mbar_a), "r"(256u) : "memory");
    }
    float c0 = 0.f, c1 = 0.f;
    const int hb = 16 * (q & 1);
    cl_sync();   // one full cluster barrier: mbarrier init + zeroed h visible everywhere

    for (int k = 0; k <= 32; k++) {
        const int pb = k & 1, nb = pb ^ 1;
        if (k < 32) {                     // gates0 for step k (reads h0[k-1])
            const float4* hv = h0p[pb];
            ull a0 = 0ull, a1 = 0ull;
            #pragma unroll
            for (int j = 0; j < 8; j += 2) {
                float4 ha = hv[hpad(8 * q + j)];
                float4 hbv = hv[hpad(8 * q + j + 1)];
                fma2(a0, w0p[2 * j],     *(ull*)&ha.x);
                fma2(a1, w0p[2 * j + 1], *(ull*)&ha.z);
                fma2(a0, w0p[2 * j + 2], *(ull*)&hbv.x);
                fma2(a1, w0p[2 * j + 3], *(ull*)&hbv.z);
            }
            float acc = upksum(a0) + upksum(a1);
            acc += __shfl_xor_sync(0xffffffffu, acc, 1, 4);
            acc += __shfl_xor_sync(0xffffffffu, acc, 2, 4);
            if (q == 0) {
                float gv = acc + bA + wih0v * xs[k];
                sg0[lr] = (gt == 2) ? tanhf(gv) : sigm(gv);   // producer-side nonlinearity
            }
        }
        if (k >= 1) {                     // gates1 for step k-1 (reads h0[k-1], h1[k-2])
            const float4* hsrc = (q < 2) ? h0p[pb] : h1p[pb];
            ull a0 = 0ull, a1 = 0ull;
            #pragma unroll
            for (int j = 0; j < 16; j += 2) {
                float4 ha = hsrc[hpad(hb + j)];
                float4 hbv = hsrc[hpad(hb + j + 1)];
                fma2(a0, w1p[2 * j],     *(ull*)&ha.x);
                fma2(a1, w1p[2 * j + 1], *(ull*)&ha.z);
                fma2(a0, w1p[2 * j + 2], *(ull*)&hbv.x);
                fma2(a1, w1p[2 * j + 3], *(ull*)&hbv.z);
            }
            float acc = upksum(a0) + upksum(a1);
            acc += __shfl_xor_sync(0xffffffffu, acc, 1, 4);
            acc += __shfl_xor_sync(0xffffffffu, acc, 2, 4);
            if (q == 0) {
                float gv = acc + bB;
                sg1[lr] = (gt == 2) ? tanhf(gv) : sigm(gv);
            }
        }
        __syncthreads();
        if (tid < 32 && k < 32) {           // h0[k] (gates already transformed)
            float gi = sg0[tid];
            float gf = sg0[32 + tid];
            float gg = sg0[64 + tid];
            float go = sg0[96 + tid];
            c0 = gf * c0 + gi * gg;
            float hval = go * tanhf(c0);
            int d = (int)rank * 32 + tid;
            float* lp = ((float*)h0p[nb]) + hpad(d >> 2) * 4 + (d & 3);
            #pragma unroll
            for (unsigned r = 0; r < 4; r++) cl_store_f32(lp, r, hval);
        }
        if (tid >= 32 && tid < 64 && k >= 1) {  // h1[k-1]
            int i = tid - 32;
            float gi = sg1[i];
            float gf = sg1[32 + i];
            float gg = sg1[64 + i];
            float go = sg1[96 + i];
            c1 = gf * c1 + gi * gg;
            float hval = go * tanhf(c1);
            int d = (int)rank * 32 + i;
            float* lp = ((float*)h1p[nb]) + hpad(d >> 2) * 4 + (d & 3);
            #pragma unroll
            for (unsigned r = 0; r < 4; r++) cl_store_f32(lp, r, hval);
        }
        // light-weight cluster handoff: 64 updater threads arrive on all 4 CTAs (count=256)
        if (tid < 64) {
            #pragma unroll
            for (unsigned r = 0; r < 4; r++) mbar_arrive_remote(mbar_a, r);
        }
        mbar_wait_cluster(mbar_a, (unsigned)(k & 1));
    }

    if (rank == 0) {                       // final projection (h1[31] in h1p[1])
        float v = 0.f;
        if (tid < 128) {
            v = ((float*)h1p[1])[hpad(tid >> 2) * 4 + (tid & 3)] * Wlin[tid];
            sg0[tid] = v;
        }
        __syncthreads();
        if (tid < 32) {
            float s = sg0[tid] + sg0[tid + 32] + sg0[tid + 64] + sg0[tid + 96];
            #pragma unroll
            for (int off = 16; off; off >>= 1) s += __shfl_xor_sync(0xffffffffu, s, off);
            if (tid == 0) out[batch] = s + blin[0];
        }
    }
    cl_sync();   // no CTA exits while peers may still target its smem
}

// ---------------- launch ----------------
extern "C" void kernel_launch(void* const* d_in, const int* in_sizes, int n_in,
                              void* d_out, int out_size) {
    const float* x     = (const float*)d_in[0];
    const int*   ei    = (const int*)d_in[1];
    const float* Wl1   = (const float*)d_in[2];
    const float* attl1 = (const float*)d_in[3];
    const float* attr1 = (const float*)d_in[4];
    const float* b1    = (const float*)d_in[5];
    const float* Wl2   = (const float*)d_in[6];
    const float* attl2 = (const float*)d_in[7];
    const float* attr2 = (const float*)d_in[8];
    const float* b2    = (const float*)d_in[9];
    const float* Wih0  = (const float*)d_in[10];
    const float* Whh0  = (const float*)d_in[11];
    const float* bih0  = (const float*)d_in[12];
    const float* bhh0  = (const float*)d_in[13];
    const float* Wih1  = (const float*)d_in[14];
    const float* Whh1  = (const float*)d_in[15];
    const float* bih1  = (const float*)d_in[16];
    const float* bhh1  = (const float*)d_in[17];
    const float* Wlin  = (const float*)d_in[18];
    const float* blin  = (const float*)d_in[19];
    float* out = (float*)d_out;

    k_pass1<<<dim3(64, T_STEPS), 256>>>(ei);
    k_pass2<<<dim3(64, T_STEPS), 256>>>(ei);
    k_gat1<<<dim3(MAX_SLOTS, T_STEPS), HID>>>(x, Wl1, attl1, attr1, b1, Wl2,
                                              attl2, attr2, b2);
    k_lstm_cl<<<128, 512>>>(Wih0, Whh0, bih0, bhh0,
                            Wih1, Whh1, bih1, bhh1, Wlin, blin, out);
}

// round 12
// speedup vs baseline: 1.0446x; 1.0436x over previous
#include <cuda_runtime.h>
#include <math.h>
#include <stdint.h>

#define T_STEPS 64
#define NN 16384
#define NE 262144
#define F_IN 8
#define H1 12
#define C1 16
#define HID 192
#define CAP0 256
#define MAX_SLOTS 64
#define CAPE 4096
#define LOCAL_CAP 128
#define P2_PRE 4
#define P2_TILE 4096                     // edges per tile (256 thr * 16)
#define P2_SMEM (16384 + P2_PRE * P2_TILE * 4)   // bitmap + staged tiles

// ---------------- scratch (static device globals; zero-initialized at load) ----------------
__device__ int   g_cnt0[T_STEPS];
__device__ int   g_e0[T_STEPS][CAP0];     // raw (atomic order) from pass1
__device__ int   g_s0[T_STEPS][CAP0];
__device__ int   g_e0s[T_STEPS][CAP0];    // canonical sorted copies (written by pass2 block0)
__device__ int   g_s0s[T_STEPS][CAP0];
__device__ int   g_slot0[T_STEPS][CAP0];
__device__ int   g_n0[T_STEPS];
__device__ int   g_scnt[T_STEPS];
__device__ int   g_S[T_STEPS][MAX_SLOTS];
__device__ int   g_incnt[T_STEPS];
__device__ int   g_ie_e[T_STEPS][CAPE];
__device__ int   g_ie_src[T_STEPS][CAPE];
__device__ int   g_ie_dst[T_STEPS][CAPE];
__device__ float g_xl2[T_STEPS][MAX_SLOTS];
__device__ float g_series[T_STEPS];
__device__ int   g_done3[T_STEPS];

__device__ __forceinline__ float lrelu(float x) { return x > 0.f ? x : 0.2f * x; }
__device__ __forceinline__ float sigm(float x) { return 1.f / (1.f + expf(-x)); }

// ---- packed fp32x2 FMA (sm_103a) ----
typedef unsigned long long ull;
__device__ __forceinline__ void fma2(ull& acc, ull w, ull h) {
    asm("fma.rn.f32x2 %0, %1, %2, %0;" : "+l"(acc) : "l"(w), "l"(h));
}
__device__ __forceinline__ ull pk2(float x, float y) {
    ull r; asm("mov.b64 %0, {%1, %2};" : "=l"(r) : "f"(x), "f"(y)); return r;
}
__device__ __forceinline__ float upksum(ull a) {
    float x, y; asm("mov.b64 {%0, %1}, %2;" : "=f"(x), "=f"(y) : "l"(a)); return x + y;
}

__device__ __forceinline__ void gdc_launch_dependents() {
    asm volatile("griddepcontrol.launch_dependents;");
}
__device__ __forceinline__ void gdc_wait() {
    asm volatile("griddepcontrol.wait;" ::: "memory");
}

__device__ __forceinline__ void edit_factor(int e, float& mul, float& add) {
    mul = 1.f; add = 0.f;
    if (e >= 0 && e < 23) {
        switch (e) {
            case 1: case 2: case 12: case 17: case 19: case 22: mul = 0.9f; break;
            case 7: case 14: mul = 0.9f; add = 0.1f; break;
            case 10: case 13: mul = 0.9f; add = 0.05f; break;
            default: break;
        }
    }
}

// ------------- K1: dst==0 scan, single-wave grid, triggers dependents early -------------
__global__ __launch_bounds__(256) void k_pass1(const int* __restrict__ ei) {
    gdc_launch_dependents();
    const int t = blockIdx.y;
    const int* __restrict__ src = ei + (size_t)t * 2 * NE;
    const int* __restrict__ dst = src + NE;
    const int base = blockIdx.x * (NE / 8);       // 8 blocks per t
    #pragma unroll 1
    for (int it = 0; it < 8; it++) {
        const int e0 = base + it * P2_TILE + threadIdx.x * 16;
        int4 v0 = *(const int4*)(dst + e0);
        int4 v1 = *(const int4*)(dst + e0 + 4);
        int4 v2 = *(const int4*)(dst + e0 + 8);
        int4 v3 = *(const int4*)(dst + e0 + 12);
        int m0 = min(min(v0.x, v0.y), min(v0.z, v0.w));
        int m1 = min(min(v1.x, v1.y), min(v1.z, v1.w));
        int m2 = min(min(v2.x, v2.y), min(v2.z, v2.w));
        int m3 = min(min(v3.x, v3.y), min(v3.z, v3.w));
        if (min(min(m0, m1), min(m2, m3)) == 0) {
            int vals[16] = { v0.x, v0.y, v0.z, v0.w, v1.x, v1.y, v1.z, v1.w,
                             v2.x, v2.y, v2.z, v2.w, v3.x, v3.y, v3.z, v3.w };
            #pragma unroll
            for (int k = 0; k < 16; k++) {
                if (vals[k] == 0) {
                    int p = atomicAdd(&g_cnt0[t], 1);
                    if (p < CAP0) { g_e0[t][p] = e0 + k; g_s0[t][p] = src[e0 + k]; }
                }
            }
        }
    }
}

// -- K2: frontier-edge scan. cp.async prefetch BEFORE griddepcontrol.wait (PDL overlap) --
__global__ __launch_bounds__(256) void k_pass2(const int* __restrict__ ei) {
    extern __shared__ __align__(16) char dynsm[];
    unsigned char* bmap = (unsigned char*)dynsm;           // 16 KB
    int* stage = (int*)(dynsm + 16384);                    // P2_PRE tiles
    __shared__ unsigned pagef[2];
    const int t = blockIdx.y;
    const int tid = threadIdx.x;
    const int* __restrict__ src = ei + (size_t)t * 2 * NE;
    const int* __restrict__ dst = src + NE;
    const int base = blockIdx.x * (NE / 8);

    // ---- pre-wait: prefetch 4 tiles via cp.async (overlaps pass1 execution) ----
    #pragma unroll
    for (int it = 0; it < P2_PRE; it++) {
        const int e0 = base + it * P2_TILE + tid * 16;
        uint32_t sa = (uint32_t)__cvta_generic_to_shared(&stage[it * P2_TILE + tid * 16]);
        #pragma unroll
        for (int j = 0; j < 4; j++)
            asm volatile("cp.async.cg.shared.global [%0], [%1], 16;"
                         :: "r"(sa + j * 16), "l"(dst + e0 + j * 4) : "memory");
    }
    asm volatile("cp.async.commit_group;" ::: "memory");
    {   // zero bitmap (independent of pass1)
        int4* bm4 = (int4*)bmap;
        int4 z = make_int4(0, 0, 0, 0);
        for (int i = tid; i < NN / 16; i += 256) bm4[i] = z;
    }
    if (tid < 2) pagef[tid] = 0;
    __syncthreads();

    gdc_wait();                                            // pass1 results now visible

    int n = g_cnt0[t]; if (n > CAP0) n = CAP0;
    if (tid < n) {
        int s = g_s0[t][tid];
        bmap[s] = 1;
        unsigned pg = (unsigned)s >> 8;
        atomicOr(&pagef[pg >> 5], 1u << (pg & 31));
    }
    if (tid == 0) { bmap[0] = 1; atomicOr(&pagef[0], 1u); }

    if (blockIdx.x == 0 && tid == 0) {   // canonical sorted structures
        int le[CAP0], ls[CAP0];
        for (int i = 0; i < n; i++) { le[i] = g_e0[t][i]; ls[i] = g_s0[t][i]; }
        for (int i = 1; i < n; i++) {
            int ke = le[i], ks = ls[i], j = i - 1;
            while (j >= 0 && le[j] > ke) { le[j + 1] = le[j]; ls[j + 1] = ls[j]; j--; }
            le[j + 1] = ke; ls[j + 1] = ks;
        }
        int sc = 1;
        g_S[t][0] = 0;
        for (int i = 0; i < n; i++) {
            int s = ls[i], slot = -1;
            for (int j = 0; j < sc; j++) if (g_S[t][j] == s) { slot = j; break; }
            if (slot < 0 && sc < MAX_SLOTS) { g_S[t][sc] = s; slot = sc; sc++; }
            g_slot0[t][i] = slot;
            g_e0s[t][i] = le[i]; g_s0s[t][i] = ls[i];
        }
        g_scnt[t] = sc;
        g_n0[t] = n;
    }
    asm volatile("cp.async.wait_group 0;" ::: "memory");
    __syncthreads();
    const unsigned pf0 = pagef[0], pf1 = pagef[1];

    // ---- probe the 4 staged tiles from smem ----
    #pragma unroll 1
    for (int it = 0; it < P2_PRE; it++) {
        const int ebase = base + it * P2_TILE + tid * 16;
        const int* vv = &stage[it * P2_TILE + tid * 16];
        #pragma unroll
        for (int k = 0; k < 16; k++) {
            int d = vv[k];
            unsigned pg = (unsigned)d >> 8;
            unsigned w = (pg >= 32) ? pf1 : pf0;
            if ((w >> (pg & 31)) & 1u) {
                if (bmap[d]) {
                    int p = atomicAdd(&g_incnt[t], 1);
                    if (p < CAPE) { g_ie_e[t][p] = ebase + k; g_ie_src[t][p] = src[ebase + k]; g_ie_dst[t][p] = d; }
                }
            }
        }
    }
    // ---- remaining 4 tiles streamed from global ----
    #pragma unroll 1
    for (int it = P2_PRE; it < 8; it++) {
        const int e0 = base + it * P2_TILE + tid * 16;
        int4 v0 = *(const int4*)(dst + e0);
        int4 v1 = *(const int4*)(dst + e0 + 4);
        int4 v2 = *(const int4*)(dst + e0 + 8);
        int4 v3 = *(const int4*)(dst + e0 + 12);
        int vals[16] = { v0.x, v0.y, v0.z, v0.w, v1.x, v1.y, v1.z, v1.w,
                         v2.x, v2.y, v2.z, v2.w, v3.x, v3.y, v3.z, v3.w };
        #pragma unroll
        for (int k = 0; k < 16; k++) {
            int d = vals[k];
            unsigned pg = (unsigned)d >> 8;
            unsigned w = (pg >= 32) ? pf1 : pf0;
            if ((w >> (pg & 31)) & 1u) {
                if (bmap[d]) {
                    int p = atomicAdd(&g_incnt[t], 1);
                    if (p < CAPE) { g_ie_e[t][p] = e0 + k; g_ie_src[t][p] = src[e0 + k]; g_ie_dst[t][p] = d; }
                }
            }
        }
    }
}

// ==== K3: GAT layer 1 at frontier nodes (+ fused layer-2 in last-finishing block) ====
__global__ void k_gat1(const float* __restrict__ x, const float* __restrict__ Wl1,
                       const float* __restrict__ attl1, const float* __restrict__ attr1,
                       const float* __restrict__ b1, const float* __restrict__ Wl2,
                       const float* __restrict__ attl2, const float* __restrict__ attr2,
                       const float* __restrict__ b2) {
    int t = blockIdx.y;
    int slot = blockIdx.x;
    int tid = threadIdx.x;              // 192 threads

    __shared__ float sWl[F_IN * HID];
    __shared__ float sAl[HID], sAr[HID], sB[HID], sW2[HID];
    __shared__ int   se[LOCAL_CAP], ss[LOCAL_CAP];
    __shared__ float sxr[LOCAL_CAP][F_IN];
    __shared__ float sal[LOCAL_CAP][H1];
    __shared__ float sm_[H1], sden[H1], sarU[H1];
    __shared__ float sfmul[LOCAL_CAP], sfadd[LOCAL_CAP];
    __shared__ float sred[HID];
    __shared__ int   sdeg;
    __shared__ int   sLast;
    __shared__ float l2xs[CAP0 + 1], l2a[CAP0 + 1];

    const int active = (slot < g_scnt[t]);
    if (active) {
        int u = g_S[t][slot];
        int h = tid >> 4, c = tid & 15;

        for (int i = tid; i < F_IN * HID; i += HID) sWl[i] = Wl1[i];
        sAl[tid] = attl1[tid]; sAr[tid] = attr1[tid]; sB[tid] = b1[tid]; sW2[tid] = Wl2[tid];
        if (tid == 0) sdeg = 0;
        __syncthreads();

        int cnt = g_incnt[t]; if (cnt > CAPE) cnt = CAPE;
        for (int i = tid; i < cnt; i += HID) {
            if (g_ie_dst[t][i] == u) {
                int p = atomicAdd(&sdeg, 1);
                if (p < LOCAL_CAP - 1) { se[p] = g_ie_e[t][i]; ss[p] = g_ie_src[t][i]; }
            }
        }
        __syncthreads();
        int deg = sdeg; if (deg > LOCAL_CAP - 1) deg = LOCAL_CAP - 1;
        if (tid == 0) {
            for (int i = 1; i < deg; i++) {                 // canonical order
                int ke = se[i], ks = ss[i], j = i - 1;
                while (j >= 0 && se[j] > ke) { se[j + 1] = se[j]; ss[j + 1] = ss[j]; j--; }
                se[j + 1] = ke; ss[j + 1] = ks;
            }
            se[deg] = 0x7fffffff; ss[deg] = u;              // self-loop last (never edited)
        }
        __syncthreads();
        int ndeg = deg + 1;

        for (int i = tid; i < ndeg * F_IN; i += HID)
            sxr[i >> 3][i & 7] = x[((size_t)t * NN + ss[i >> 3]) * F_IN + (i & 7)];
        __syncthreads();

        {   // ar_u from xl1[u] (self row at index deg)
            float v = 0.f;
            #pragma unroll
            for (int k = 0; k < F_IN; k++) v += sxr[deg][k] * sWl[k * HID + tid];
            float r = v * sAr[tid];
            #pragma unroll
            for (int off = 8; off; off >>= 1) r += __shfl_xor_sync(0xffffffffu, r, off, 16);
            if (c == 0) sarU[h] = r;
        }
        for (int i = 0; i < ndeg; i++) {
            float v = 0.f;
            #pragma unroll
            for (int k = 0; k < F_IN; k++) v += sxr[i][k] * sWl[k * HID + tid];
            float a = v * sAl[tid];
            #pragma unroll
            for (int off = 8; off; off >>= 1) a += __shfl_xor_sync(0xffffffffu, a, off, 16);
            if (c == 0) sal[i][h] = a;
        }
        __syncthreads();

        if (tid < H1) {
            int hh = tid;
            float m = -1e30f;
            for (int i = 0; i < ndeg; i++) { float a = lrelu(sal[i][hh] + sarU[hh]); if (a > m) m = a; }
            float den = 0.f;
            for (int i = 0; i < ndeg; i++) den += expf(lrelu(sal[i][hh] + sarU[hh]) - m);
            sm_[hh] = m; sden[hh] = den + 1e-16f;
        }
        if (tid >= 32 && tid < 32 + ndeg) {
            int i = tid - 32; float mu, ad; edit_factor(se[i], mu, ad); sfmul[i] = mu; sfadd[i] = ad;
        }
        __syncthreads();

        float acc = 0.f;
        for (int i = 0; i < ndeg; i++) {
            float a = lrelu(sal[i][h] + sarU[h]);
            float alpha = expf(a - sm_[h]) / sden[h];
            alpha = sfmul[i] * alpha + sfadd[i];
            float v = 0.f;
            #pragma unroll
            for (int k = 0; k < F_IN; k++) v += sxr[i][k] * sWl[k * HID + tid];
            acc += alpha * v;
        }
        acc += sB[tid];
        float e1 = acc > 0.f ? acc : (expf(acc) - 1.f);      // ELU
        sred[tid] = e1 * sW2[tid];
        __syncthreads();
        if (tid < 64) sred[tid] = sred[tid] + sred[tid + 64] + sred[tid + 128];
        __syncthreads();
        if (tid < 32) {
            float v = sred[tid] + sred[tid + 32];
            #pragma unroll
            for (int off = 16; off; off >>= 1) v += __shfl_xor_sync(0xffffffffu, v, off);
            if (tid == 0) g_xl2[t][slot] = v;
        }
    }

    // -------- completion counter; last block of this t runs GAT layer 2 --------
    __syncthreads();
    if (tid == 0) {
        __threadfence();
        int old = atomicAdd(&g_done3[t], 1);
        sLast = (old == gridDim.x - 1) ? 1 : 0;
        if (sLast) __threadfence();
    }
    __syncthreads();
    if (sLast) {
        int n = g_n0[t];
        if (tid < 32) {
            float al2 = attl2[0], ar2v = attr2[0];
            float x0 = *(volatile float*)&g_xl2[t][0];
            float ar0 = x0 * ar2v;
            float m = -1e30f;
            for (int i = tid; i <= n; i += 32) {
                float xs = (i < n) ? *(volatile float*)&g_xl2[t][g_slot0[t][i]] : x0;
                float a = lrelu(xs * al2 + ar0);
                l2xs[i] = xs; l2a[i] = a;
                m = fmaxf(m, a);
            }
            __syncwarp();
            #pragma unroll
            for (int off = 16; off; off >>= 1) m = fmaxf(m, __shfl_xor_sync(0xffffffffu, m, off));
            float den = 0.f;
            for (int i = tid; i <= n; i += 32) den += expf(l2a[i] - m);
            #pragma unroll
            for (int off = 16; off; off >>= 1) den += __shfl_xor_sync(0xffffffffu, den, off);
            den += 1e-16f;
            float outv = 0.f;
            for (int i = tid; i <= n; i += 32) {
                float alpha = expf(l2a[i] - m) / den;
                int e = (i < n) ? g_e0s[t][i] : 0x7fffffff;
                float mu, ad; edit_factor(e, mu, ad);
                outv += (mu * alpha + ad) * l2xs[i];
            }
            #pragma unroll
            for (int off = 16; off; off >>= 1) outv += __shfl_xor_sync(0xffffffffu, outv, off);
            if (tid == 0) {
                g_series[t] = outv + b2[0];
                g_cnt0[t] = 0; g_incnt[t] = 0; g_done3[t] = 0;   // reset for next replay
            }
        }
    }
}

// ========= K4: cluster-4 LSTM (R8 sync) + producer nonlinearities + local self-store =========
__device__ __forceinline__ int hpad(int k4) { return k4 + (k4 >> 3); }
__device__ __forceinline__ unsigned cl_rank() {
    unsigned r; asm("mov.u32 %0, %%cluster_ctarank;" : "=r"(r)); return r;
}
__device__ __forceinline__ void cl_sync() {
    asm volatile("barrier.cluster.arrive.aligned;\n\tbarrier.cluster.wait.aligned;" ::: "memory");
}
__device__ __forceinline__ void cl_store_f32(float* p, unsigned rank, float v) {
    uint32_t a = (uint32_t)__cvta_generic_to_shared(p);
    uint32_t pa;
    asm("mapa.shared::cluster.u32 %0, %1, %2;" : "=r"(pa) : "r"(a), "r"(rank));
    asm volatile("st.shared::cluster.f32 [%0], %1;" :: "r"(pa), "f"(v) : "memory");
}

__global__ void __cluster_dims__(4, 1, 1) __launch_bounds__(512, 1)
k_lstm_cl(const float* __restrict__ Wih0, const float* __restrict__ Whh0,
          const float* __restrict__ bih0, const float* __restrict__ bhh0,
          const float* __restrict__ Wih1, const float* __restrict__ Whh1,
          const float* __restrict__ bih1, const float* __restrict__ bhh1,
          const float* __restrict__ Wlin, const float* __restrict__ blin,
          float* __restrict__ out) {
    __shared__ __align__(16) float4 h0p[2][36];
    __shared__ __align__(16) float4 h1p[2][36];
    __shared__ float sg0[128], sg1[128];
    __shared__ float xs[32];

    const unsigned rank = cl_rank();
    const int batch = blockIdx.x >> 2;
    const int tid = threadIdx.x;
    const int lr = tid >> 2, q = tid & 3;            // row 0..127, k-quarter
    const int gt = lr >> 5, dl = lr & 31;
    const int gr = gt * 128 + (int)rank * 32 + dl;   // global gate row

    ull w0p[16], w1p[32];
    {
        const float4* W0 = (const float4*)(Whh0 + (size_t)gr * 128) + 8 * q;
        #pragma unroll
        for (int j = 0; j < 8; j++) {
            float4 w = W0[j];
            w0p[2 * j] = pk2(w.x, w.y); w0p[2 * j + 1] = pk2(w.z, w.w);
        }
        const float* Wsrc = (q < 2) ? Wih1 : Whh1;
        const float4* W1 = (const float4*)(Wsrc + (size_t)gr * 128) + 16 * (q & 1);
        #pragma unroll
        for (int j = 0; j < 16; j++) {
            float4 w = W1[j];
            w1p[2 * j] = pk2(w.x, w.y); w1p[2 * j + 1] = pk2(w.z, w.w);
        }
    }
    float wih0v = 0.f, bA = 0.f, bB = 0.f;
    if (q == 0) { wih0v = Wih0[gr]; bA = bih0[gr] + bhh0[gr]; bB = bih1[gr] + bhh1[gr]; }
    if (tid < 32) xs[tid] = g_series[batch + tid];
    {
        float* hz = (float*)&h0p[0][0];
        for (int i = tid; i < 2 * 2 * 36 * 4; i += 512) hz[i] = 0.f;
    }
    float c0 = 0.f, c1 = 0.f;
    const int hb = 16 * (q & 1);
    cl_sync();

    for (int k = 0; k <= 32; k++) {
        const int pb = k & 1, nb = pb ^ 1;
        if (k < 32) {                     // gates0 for step k (reads h0[k-1])
            const float4* hv = h0p[pb];
            ull a0 = 0ull, a1 = 0ull;
            #pragma unroll
            for (int j = 0; j < 8; j += 2) {
                float4 ha = hv[hpad(8 * q + j)];
                float4 hbv = hv[hpad(8 * q + j + 1)];
                fma2(a0, w0p[2 * j],     *(ull*)&ha.x);
                fma2(a1, w0p[2 * j + 1], *(ull*)&ha.z);
                fma2(a0, w0p[2 * j + 2], *(ull*)&hbv.x);
                fma2(a1, w0p[2 * j + 3], *(ull*)&hbv.z);
            }
            float acc = upksum(a0) + upksum(a1);
            acc += __shfl_xor_sync(0xffffffffu, acc, 1, 4);
            acc += __shfl_xor_sync(0xffffffffu, acc, 2, 4);
            if (q == 0) {
                float gv = acc + bA + wih0v * xs[k];
                sg0[lr] = (gt == 2) ? tanhf(gv) : sigm(gv);   // producer-side nonlinearity
            }
        }
        if (k >= 1) {                     // gates1 for step k-1 (reads h0[k-1], h1[k-2])
            const float4* hsrc = (q < 2) ? h0p[pb] : h1p[pb];
            ull a0 = 0ull, a1 = 0ull;
            #pragma unroll
            for (int j = 0; j < 16; j += 2) {
                float4 ha = hsrc[hpad(hb + j)];
                float4 hbv = hsrc[hpad(hb + j + 1)];
                fma2(a0, w1p[2 * j],     *(ull*)&ha.x);
                fma2(a1, w1p[2 * j + 1], *(ull*)&ha.z);
                fma2(a0, w1p[2 * j + 2], *(ull*)&hbv.x);
                fma2(a1, w1p[2 * j + 3], *(ull*)&hbv.z);
            }
            float acc = upksum(a0) + upksum(a1);
            acc += __shfl_xor_sync(0xffffffffu, acc, 1, 4);
            acc += __shfl_xor_sync(0xffffffffu, acc, 2, 4);
            if (q == 0) {
                float gv = acc + bB;
                sg1[lr] = (gt == 2) ? tanhf(gv) : sigm(gv);
            }
        }
        __syncthreads();
        if (tid < 32 && k < 32) {           // h0[k] (gates pre-transformed)
            float gi = sg0[tid];
            float gf = sg0[32 + tid];
            float gg = sg0[64 + tid];
            float go = sg0[96 + tid];
            c0 = gf * c0 + gi * gg;
            float hval = go * tanhf(c0);
            int d = (int)rank * 32 + tid;
            float* lp = ((float*)h0p[nb]) + hpad(d >> 2) * 4 + (d & 3);
            lp[0] = hval;                                   // local store
            #pragma unroll
            for (unsigned r = 1; r < 4; r++) cl_store_f32(lp, (rank + r) & 3, hval);
        }
        if (tid >= 32 && tid < 64 && k >= 1) {  // h1[k-1]
            int i = tid - 32;
            float gi = sg1[i];
            float gf = sg1[32 + i];
            float gg = sg1[64 + i];
            float go = sg1[96 + i];
            c1 = gf * c1 + gi * gg;
            float hval = go * tanhf(c1);
            int d = (int)rank * 32 + i;
            float* lp = ((float*)h1p[nb]) + hpad(d >> 2) * 4 + (d & 3);
            lp[0] = hval;
            #pragma unroll
            for (unsigned r = 1; r < 4; r++) cl_store_f32(lp, (rank + r) & 3, hval);
        }
        cl_sync();
    }

    if (rank == 0) {                       // final projection (h1[31] in h1p[1])
        float v = 0.f;
        if (tid < 128) {
            v = ((float*)h1p[1])[hpad(tid >> 2) * 4 + (tid & 3)] * Wlin[tid];
            sg0[tid] = v;
        }
        __syncthreads();
        if (tid < 32) {
            float s = sg0[tid] + sg0[tid + 32] + sg0[tid + 64] + sg0[tid + 96];
            #pragma unroll
            for (int off = 16; off; off >>= 1) s += __shfl_xor_sync(0xffffffffu, s, off);
            if (tid == 0) out[batch] = s + blin[0];
        }
    }
    cl_sync();   // no CTA exits while peers may still target its smem
}

// ---------------- launch ----------------
extern "C" void kernel_launch(void* const* d_in, const int* in_sizes, int n_in,
                              void* d_out, int out_size) {
    const float* x     = (const float*)d_in[0];
    const int*   ei    = (const int*)d_in[1];
    const float* Wl1   = (const float*)d_in[2];
    const float* attl1 = (const float*)d_in[3];
    const float* attr1 = (const float*)d_in[4];
    const float* b1    = (const float*)d_in[5];
    const float* Wl2   = (const float*)d_in[6];
    const float* attl2 = (const float*)d_in[7];
    const float* attr2 = (const float*)d_in[8];
    const float* b2    = (const float*)d_in[9];
    const float* Wih0  = (const float*)d_in[10];
    const float* Whh0  = (const float*)d_in[11];
    const float* bih0  = (const float*)d_in[12];
    const float* bhh0  = (const float*)d_in[13];
    const float* Wih1  = (const float*)d_in[14];
    const float* Whh1  = (const float*)d_in[15];
    const float* bih1  = (const float*)d_in[16];
    const float* bhh1  = (const float*)d_in[17];
    const float* Wlin  = (const float*)d_in[18];
    const float* blin  = (const float*)d_in[19];
    float* out = (float*)d_out;

    cudaFuncSetAttribute(k_pass2, cudaFuncAttributeMaxDynamicSharedMemorySize, P2_SMEM);

    k_pass1<<<dim3(8, T_STEPS), 256>>>(ei);

    {   // pass2 with programmatic dependent launch: prefetch overlaps pass1
        cudaLaunchConfig_t cfg = {};
        cfg.gridDim = dim3(8, T_STEPS);
        cfg.blockDim = dim3(256);
        cfg.dynamicSmemBytes = P2_SMEM;
        cfg.stream = 0;
        cudaLaunchAttribute attr[1];
        attr[0].id = cudaLaunchAttributeProgrammaticStreamSerialization;
        attr[0].val.programmaticStreamSerializationAllowed = 1;
        cfg.attrs = attr;
        cfg.numAttrs = 1;
        void* args[] = { (void*)&ei };
        cudaLaunchKernelExC(&cfg, (const void*)k_pass2, args);
    }

    k_gat1<<<dim3(MAX_SLOTS, T_STEPS), HID>>>(x, Wl1, attl1, attr1, b1, Wl2,
                                              attl2, attr2, b2);
    k_lstm_cl<<<128, 512>>>(Wih0, Whh0, bih0, bhh0,
                            Wih1, Whh1, bih1, bhh1, Wlin, blin, out);
}

// round 13
// speedup vs baseline: 1.0921x; 1.0454x over previous
#include <cuda_runtime.h>
#include <math.h>
#include <stdint.h>

#define T_STEPS 64
#define NN 16384
#define NE 262144
#define F_IN 8
#define H1 12
#define C1 16
#define HID 192
#define CAP0 256
#define MAX_SLOTS 64
#define CAPE 4096
#define LOCAL_CAP 128

// ---------------- scratch (static device globals; zero-initialized at load) ----------------
__device__ int   g_cnt0[T_STEPS];
__device__ int   g_e0[T_STEPS][CAP0];     // raw (atomic order) from pass1
__device__ int   g_s0[T_STEPS][CAP0];
__device__ int   g_e0s[T_STEPS][CAP0];    // canonical sorted copies (written by pass2 block0)
__device__ int   g_s0s[T_STEPS][CAP0];
__device__ int   g_slot0[T_STEPS][CAP0];
__device__ int   g_n0[T_STEPS];
__device__ int   g_scnt[T_STEPS];
__device__ int   g_S[T_STEPS][MAX_SLOTS];
__device__ int   g_incnt[T_STEPS];
__device__ int   g_ie_e[T_STEPS][CAPE];
__device__ int   g_ie_src[T_STEPS][CAPE];
__device__ int   g_ie_dst[T_STEPS][CAPE];
__device__ float g_xl2[T_STEPS][MAX_SLOTS];
__device__ float g_series[T_STEPS];
__device__ int   g_done3[T_STEPS];

__device__ __forceinline__ float lrelu(float x) { return x > 0.f ? x : 0.2f * x; }
__device__ __forceinline__ float sigm(float x) { return 1.f / (1.f + expf(-x)); }

// ---- packed fp32x2 FMA (sm_103a) ----
typedef unsigned long long ull;
__device__ __forceinline__ void fma2(ull& acc, ull w, ull h) {
    asm("fma.rn.f32x2 %0, %1, %2, %0;" : "+l"(acc) : "l"(w), "l"(h));
}
__device__ __forceinline__ ull pk2(float x, float y) {
    ull r; asm("mov.b64 %0, {%1, %2};" : "=l"(r) : "f"(x), "f"(y)); return r;
}
__device__ __forceinline__ float upksum(ull a) {
    float x, y; asm("mov.b64 {%0, %1}, %2;" : "=f"(x), "=f"(y) : "l"(a)); return x + y;
}

__device__ __forceinline__ void edit_factor(int e, float& mul, float& add) {
    mul = 1.f; add = 0.f;
    if (e >= 0 && e < 23) {
        switch (e) {
            case 1: case 2: case 12: case 17: case 19: case 22: mul = 0.9f; break;
            case 7: case 14: mul = 0.9f; add = 0.1f; break;
            case 10: case 13: mul = 0.9f; add = 0.05f; break;
            default: break;
        }
    }
}

// ------------- K1: find edges with dst == 0 (16 vals/thread, min-tree) -------------
__global__ void k_pass1(const int* __restrict__ ei) {
    const int t = blockIdx.y;
    const int* __restrict__ src = ei + (size_t)t * 2 * NE;
    const int* __restrict__ dst = src + NE;
    const int e0 = blockIdx.x * (256 * 16) + threadIdx.x * 16;
    int4 v0 = *(const int4*)(dst + e0);
    int4 v1 = *(const int4*)(dst + e0 + 4);
    int4 v2 = *(const int4*)(dst + e0 + 8);
    int4 v3 = *(const int4*)(dst + e0 + 12);
    int m0 = min(min(v0.x, v0.y), min(v0.z, v0.w));
    int m1 = min(min(v1.x, v1.y), min(v1.z, v1.w));
    int m2 = min(min(v2.x, v2.y), min(v2.z, v2.w));
    int m3 = min(min(v3.x, v3.y), min(v3.z, v3.w));
    if (min(min(m0, m1), min(m2, m3)) == 0) {
        int vals[16] = { v0.x, v0.y, v0.z, v0.w, v1.x, v1.y, v1.z, v1.w,
                         v2.x, v2.y, v2.z, v2.w, v3.x, v3.y, v3.z, v3.w };
        #pragma unroll
        for (int k = 0; k < 16; k++) {
            if (vals[k] == 0) {
                int p = atomicAdd(&g_cnt0[t], 1);
                if (p < CAP0) { g_e0[t][p] = e0 + k; g_s0[t][p] = src[e0 + k]; }
            }
        }
    }
}

// -- K2: edges into frontier set (page filter + byte-map; canonical build merged in) --
__global__ void k_pass2(const int* __restrict__ ei) {
    __shared__ unsigned char bmap[NN];   // 16 KB membership byte map
    __shared__ unsigned pagef[2];        // 64-bit page filter (256-node pages)
    const int t = blockIdx.y;
    {
        int4* bm4 = (int4*)bmap;
        int4 z = make_int4(0, 0, 0, 0);
        for (int i = threadIdx.x; i < NN / 16; i += 256) bm4[i] = z;
    }
    if (threadIdx.x < 2) pagef[threadIdx.x] = 0;
    __syncthreads();
    int n = g_cnt0[t]; if (n > CAP0) n = CAP0;
    if (threadIdx.x < n) {
        int s = g_s0[t][threadIdx.x];
        bmap[s] = 1;
        unsigned pg = (unsigned)s >> 8;
        atomicOr(&pagef[pg >> 5], 1u << (pg & 31));
    }
    if (threadIdx.x == 0) {               // node 0 itself
        bmap[0] = 1;
        atomicOr(&pagef[0], 1u);
    }

    // block x==0, thread 0: build canonical sorted structures (separate arrays -> no race)
    if (blockIdx.x == 0 && threadIdx.x == 0) {
        int le[CAP0], ls[CAP0];
        for (int i = 0; i < n; i++) { le[i] = g_e0[t][i]; ls[i] = g_s0[t][i]; }
        for (int i = 1; i < n; i++) {
            int ke = le[i], ks = ls[i], j = i - 1;
            while (j >= 0 && le[j] > ke) { le[j + 1] = le[j]; ls[j + 1] = ls[j]; j--; }
            le[j + 1] = ke; ls[j + 1] = ks;
        }
        int sc = 1;
        g_S[t][0] = 0;
        for (int i = 0; i < n; i++) {
            int s = ls[i], slot = -1;
            for (int j = 0; j < sc; j++) if (g_S[t][j] == s) { slot = j; break; }
            if (slot < 0 && sc < MAX_SLOTS) { g_S[t][sc] = s; slot = sc; sc++; }
            g_slot0[t][i] = slot;
            g_e0s[t][i] = le[i]; g_s0s[t][i] = ls[i];
        }
        g_scnt[t] = sc;
        g_n0[t] = n;
    }
    __syncthreads();
    const unsigned pf0 = pagef[0], pf1 = pagef[1];

    const int* __restrict__ src = ei + (size_t)t * 2 * NE;
    const int* __restrict__ dst = src + NE;
    const int e0 = blockIdx.x * (256 * 16) + threadIdx.x * 16;
    int4 v0 = *(const int4*)(dst + e0);
    int4 v1 = *(const int4*)(dst + e0 + 4);
    int4 v2 = *(const int4*)(dst + e0 + 8);
    int4 v3 = *(const int4*)(dst + e0 + 12);
    int vals[16] = { v0.x, v0.y, v0.z, v0.w, v1.x, v1.y, v1.z, v1.w,
                     v2.x, v2.y, v2.z, v2.w, v3.x, v3.y, v3.z, v3.w };
    #pragma unroll
    for (int k = 0; k < 16; k++) {
        int d = vals[k];
        unsigned pg = (unsigned)d >> 8;
        unsigned w = (pg >= 32) ? pf1 : pf0;
        if ((w >> (pg & 31)) & 1u) {
            if (bmap[d]) {
                int p = atomicAdd(&g_incnt[t], 1);
                if (p < CAPE) { g_ie_e[t][p] = e0 + k; g_ie_src[t][p] = src[e0 + k]; g_ie_dst[t][p] = d; }
            }
        }
    }
}

// ==== K3: GAT layer 1 at frontier nodes (+ fused layer-2 in last-finishing block) ====
__global__ void k_gat1(const float* __restrict__ x, const float* __restrict__ Wl1,
                       const float* __restrict__ attl1, const float* __restrict__ attr1,
                       const float* __restrict__ b1, const float* __restrict__ Wl2,
                       const float* __restrict__ attl2, const float* __restrict__ attr2,
                       const float* __restrict__ b2) {
    int t = blockIdx.y;
    int slot = blockIdx.x;
    int tid = threadIdx.x;              // 192 threads

    __shared__ float sWl[F_IN * HID];
    __shared__ float sAl[HID], sAr[HID], sB[HID], sW2[HID];
    __shared__ int   se[LOCAL_CAP], ss[LOCAL_CAP];
    __shared__ float sxr[LOCAL_CAP][F_IN];
    __shared__ float sal[LOCAL_CAP][H1];
    __shared__ float sm_[H1], sden[H1], sarU[H1];
    __shared__ float sfmul[LOCAL_CAP], sfadd[LOCAL_CAP];
    __shared__ float sred[HID];
    __shared__ int   sdeg;
    __shared__ int   sLast;
    __shared__ float l2xs[CAP0 + 1], l2a[CAP0 + 1];

    const int active = (slot < g_scnt[t]);
    if (active) {
        int u = g_S[t][slot];
        int h = tid >> 4, c = tid & 15;

        for (int i = tid; i < F_IN * HID; i += HID) sWl[i] = Wl1[i];
        sAl[tid] = attl1[tid]; sAr[tid] = attr1[tid]; sB[tid] = b1[tid]; sW2[tid] = Wl2[tid];
        if (tid == 0) sdeg = 0;
        __syncthreads();

        int cnt = g_incnt[t]; if (cnt > CAPE) cnt = CAPE;
        for (int i = tid; i < cnt; i += HID) {
            if (g_ie_dst[t][i] == u) {
                int p = atomicAdd(&sdeg, 1);
                if (p < LOCAL_CAP - 1) { se[p] = g_ie_e[t][i]; ss[p] = g_ie_src[t][i]; }
            }
        }
        __syncthreads();
        int deg = sdeg; if (deg > LOCAL_CAP - 1) deg = LOCAL_CAP - 1;
        if (tid == 0) {
            for (int i = 1; i < deg; i++) {                 // canonical order
                int ke = se[i], ks = ss[i], j = i - 1;
                while (j >= 0 && se[j] > ke) { se[j + 1] = se[j]; ss[j + 1] = ss[j]; j--; }
                se[j + 1] = ke; ss[j + 1] = ks;
            }
            se[deg] = 0x7fffffff; ss[deg] = u;              // self-loop last (never edited)
        }
        __syncthreads();
        int ndeg = deg + 1;

        for (int i = tid; i < ndeg * F_IN; i += HID)
            sxr[i >> 3][i & 7] = x[((size_t)t * NN + ss[i >> 3]) * F_IN + (i & 7)];
        __syncthreads();

        {   // ar_u from xl1[u] (self row at index deg)
            float v = 0.f;
            #pragma unroll
            for (int k = 0; k < F_IN; k++) v += sxr[deg][k] * sWl[k * HID + tid];
            float r = v * sAr[tid];
            #pragma unroll
            for (int off = 8; off; off >>= 1) r += __shfl_xor_sync(0xffffffffu, r, off, 16);
            if (c == 0) sarU[h] = r;
        }
        for (int i = 0; i < ndeg; i++) {
            float v = 0.f;
            #pragma unroll
            for (int k = 0; k < F_IN; k++) v += sxr[i][k] * sWl[k * HID + tid];
            float a = v * sAl[tid];
            #pragma unroll
            for (int off = 8; off; off >>= 1) a += __shfl_xor_sync(0xffffffffu, a, off, 16);
            if (c == 0) sal[i][h] = a;
        }
        __syncthreads();

        if (tid < H1) {
            int hh = tid;
            float m = -1e30f;
            for (int i = 0; i < ndeg; i++) { float a = lrelu(sal[i][hh] + sarU[hh]); if (a > m) m = a; }
            float den = 0.f;
            for (int i = 0; i < ndeg; i++) den += expf(lrelu(sal[i][hh] + sarU[hh]) - m);
            sm_[hh] = m; sden[hh] = den + 1e-16f;
        }
        if (tid >= 32 && tid < 32 + ndeg) {
            int i = tid - 32; float mu, ad; edit_factor(se[i], mu, ad); sfmul[i] = mu; sfadd[i] = ad;
        }
        __syncthreads();

        float acc = 0.f;
        for (int i = 0; i < ndeg; i++) {
            float a = lrelu(sal[i][h] + sarU[h]);
            float alpha = expf(a - sm_[h]) / sden[h];
            alpha = sfmul[i] * alpha + sfadd[i];
            float v = 0.f;
            #pragma unroll
            for (int k = 0; k < F_IN; k++) v += sxr[i][k] * sWl[k * HID + tid];
            acc += alpha * v;
        }
        acc += sB[tid];
        float e1 = acc > 0.f ? acc : (expf(acc) - 1.f);      // ELU
        sred[tid] = e1 * sW2[tid];
        __syncthreads();
        if (tid < 64) sred[tid] = sred[tid] + sred[tid + 64] + sred[tid + 128];
        __syncthreads();
        if (tid < 32) {
            float v = sred[tid] + sred[tid + 32];
            #pragma unroll
            for (int off = 16; off; off >>= 1) v += __shfl_xor_sync(0xffffffffu, v, off);
            if (tid == 0) g_xl2[t][slot] = v;
        }
    }

    // -------- completion counter; last block of this t runs GAT layer 2 --------
    __syncthreads();
    if (tid == 0) {
        __threadfence();
        int old = atomicAdd(&g_done3[t], 1);
        sLast = (old == gridDim.x - 1) ? 1 : 0;
        if (sLast) __threadfence();
    }
    __syncthreads();
    if (sLast) {
        int n = g_n0[t];
        if (tid < 32) {
            float al2 = attl2[0], ar2v = attr2[0];
            float x0 = *(volatile float*)&g_xl2[t][0];
            float ar0 = x0 * ar2v;
            float m = -1e30f;
            for (int i = tid; i <= n; i += 32) {
                float xs = (i < n) ? *(volatile float*)&g_xl2[t][g_slot0[t][i]] : x0;
                float a = lrelu(xs * al2 + ar0);
                l2xs[i] = xs; l2a[i] = a;
                m = fmaxf(m, a);
            }
            __syncwarp();
            #pragma unroll
            for (int off = 16; off; off >>= 1) m = fmaxf(m, __shfl_xor_sync(0xffffffffu, m, off));
            float den = 0.f;
            for (int i = tid; i <= n; i += 32) den += expf(l2a[i] - m);
            #pragma unroll
            for (int off = 16; off; off >>= 1) den += __shfl_xor_sync(0xffffffffu, den, off);
            den += 1e-16f;
            float outv = 0.f;
            for (int i = tid; i <= n; i += 32) {
                float alpha = expf(l2a[i] - m) / den;
                int e = (i < n) ? g_e0s[t][i] : 0x7fffffff;
                float mu, ad; edit_factor(e, mu, ad);
                outv += (mu * alpha + ad) * l2xs[i];
            }
            #pragma unroll
            for (int off = 16; off; off >>= 1) outv += __shfl_xor_sync(0xffffffffu, outv, off);
            if (tid == 0) {
                g_series[t] = outv + b2[0];
                g_cnt0[t] = 0; g_incnt[t] = 0; g_done3[t] = 0;   // reset for next replay
            }
        }
    }
}

// ===== K4: cluster-4 LSTM, reg weights, SPLIT arrive/wait with pre-wait local matvec =====
__device__ __forceinline__ int hpad(int k4) { return k4 + (k4 >> 3); }
__device__ __forceinline__ unsigned cl_rank() {
    unsigned r; asm("mov.u32 %0, %%cluster_ctarank;" : "=r"(r)); return r;
}
__device__ __forceinline__ void cl_sync() {
    asm volatile("barrier.cluster.arrive.aligned;\n\tbarrier.cluster.wait.aligned;" ::: "memory");
}
__device__ __forceinline__ void cl_arrive() {
    asm volatile("barrier.cluster.arrive.aligned;" ::: "memory");
}
__device__ __forceinline__ void cl_wait() {
    asm volatile("barrier.cluster.wait.aligned;" ::: "memory");
}
__device__ __forceinline__ void cl_store_f32(float* p, unsigned rank, float v) {
    uint32_t a = (uint32_t)__cvta_generic_to_shared(p);
    uint32_t pa;
    asm("mapa.shared::cluster.u32 %0, %1, %2;" : "=r"(pa) : "r"(a), "r"(rank));
    asm volatile("st.shared::cluster.f32 [%0], %1;" :: "r"(pa), "f"(v) : "memory");
}

__global__ void __cluster_dims__(4, 1, 1) __launch_bounds__(512, 1)
k_lstm_cl(const float* __restrict__ Wih0, const float* __restrict__ Whh0,
          const float* __restrict__ bih0, const float* __restrict__ bhh0,
          const float* __restrict__ Wih1, const float* __restrict__ Whh1,
          const float* __restrict__ bih1, const float* __restrict__ bhh1,
          const float* __restrict__ Wlin, const float* __restrict__ blin,
          float* __restrict__ out) {
    __shared__ __align__(16) float4 h0p[2][36];
    __shared__ __align__(16) float4 h1p[2][36];
    __shared__ float sg0[128], sg1[128];
    __shared__ float xs[32];

    const unsigned rank = cl_rank();
    const int batch = blockIdx.x >> 2;
    const int tid = threadIdx.x;
    const int lr = tid >> 2, q = tid & 3;            // row 0..127, k-quarter
    const int gt = lr >> 5, dl = lr & 31;
    const int gr = gt * 128 + (int)rank * 32 + dl;   // global gate row
    const bool pre_ok = (q == (int)rank);            // this thread's h-quarter is produced locally

    ull w0p[16], w1p[32];
    {
        const float4* W0 = (const float4*)(Whh0 + (size_t)gr * 128) + 8 * q;
        #pragma unroll
        for (int j = 0; j < 8; j++) {
            float4 w = W0[j];
            w0p[2 * j] = pk2(w.x, w.y); w0p[2 * j + 1] = pk2(w.z, w.w);
        }
        const float* Wsrc = (q < 2) ? Wih1 : Whh1;
        const float4* W1 = (const float4*)(Wsrc + (size_t)gr * 128) + 16 * (q & 1);
        #pragma unroll
        for (int j = 0; j < 16; j++) {
            float4 w = W1[j];
            w1p[2 * j] = pk2(w.x, w.y); w1p[2 * j + 1] = pk2(w.z, w.w);
        }
    }
    float wih0v = 0.f, bA = 0.f, bB = 0.f;
    if (q == 0) { wih0v = Wih0[gr]; bA = bih0[gr] + bhh0[gr]; bB = bih1[gr] + bhh1[gr]; }
    if (tid < 32) xs[tid] = g_series[batch + tid];
    {
        float* hz = (float*)&h0p[0][0];
        for (int i = tid; i < 2 * 2 * 36 * 4; i += 512) hz[i] = 0.f;
    }
    float c0 = 0.f, c1 = 0.f;
    const int hb = 16 * (q & 1);
    cl_sync();      // init visible everywhere
    cl_arrive();    // pre-arm the k=0 wait

    for (int k = 0; k <= 32; k++) {
        const int pb = k & 1, nb = pb ^ 1;

        // ---- pre-wait: gates0 partial over the LOCALLY-produced h quarter ----
        ull a0 = 0ull, a1 = 0ull;
        if (k < 32 && pre_ok) {
            const float4* hv = h0p[pb];
            #pragma unroll
            for (int j = 0; j < 8; j += 2) {
                float4 ha = hv[hpad(8 * q + j)];
                float4 hbv = hv[hpad(8 * q + j + 1)];
                fma2(a0, w0p[2 * j],     *(ull*)&ha.x);
                fma2(a1, w0p[2 * j + 1], *(ull*)&ha.z);
                fma2(a0, w0p[2 * j + 2], *(ull*)&hbv.x);
                fma2(a1, w0p[2 * j + 3], *(ull*)&hbv.z);
            }
        }
        cl_wait();   // peer h stores from previous phase now visible

        if (k < 32) {                     // gates0 for step k (reads h0[k-1])
            if (!pre_ok) {
                const float4* hv = h0p[pb];
                #pragma unroll
                for (int j = 0; j < 8; j += 2) {
                    float4 ha = hv[hpad(8 * q + j)];
                    float4 hbv = hv[hpad(8 * q + j + 1)];
                    fma2(a0, w0p[2 * j],     *(ull*)&ha.x);
                    fma2(a1, w0p[2 * j + 1], *(ull*)&ha.z);
                    fma2(a0, w0p[2 * j + 2], *(ull*)&hbv.x);
                    fma2(a1, w0p[2 * j + 3], *(ull*)&hbv.z);
                }
            }
            float acc = upksum(a0) + upksum(a1);
            acc += __shfl_xor_sync(0xffffffffu, acc, 1, 4);
            acc += __shfl_xor_sync(0xffffffffu, acc, 2, 4);
            if (q == 0) {
                float gv = acc + bA + wih0v * xs[k];
                sg0[lr] = (gt == 2) ? tanhf(gv) : sigm(gv);   // producer-side nonlinearity
            }
        }
        if (k >= 1) {                     // gates1 for step k-1 (reads h0[k-1], h1[k-2])
            const float4* hsrc = (q < 2) ? h0p[pb] : h1p[pb];
            ull b0 = 0ull, b1v = 0ull;
            #pragma unroll
            for (int j = 0; j < 16; j += 2) {
                float4 ha = hsrc[hpad(hb + j)];
                float4 hbv = hsrc[hpad(hb + j + 1)];
                fma2(b0,  w1p[2 * j],     *(ull*)&ha.x);
                fma2(b1v, w1p[2 * j + 1], *(ull*)&ha.z);
                fma2(b0,  w1p[2 * j + 2], *(ull*)&hbv.x);
                fma2(b1v, w1p[2 * j + 3], *(ull*)&hbv.z);
            }
            float acc = upksum(b0) + upksum(b1v);
            acc += __shfl_xor_sync(0xffffffffu, acc, 1, 4);
            acc += __shfl_xor_sync(0xffffffffu, acc, 2, 4);
            if (q == 0) {
                float gv = acc + bB;
                sg1[lr] = (gt == 2) ? tanhf(gv) : sigm(gv);
            }
        }
        __syncthreads();
        if (tid < 32 && k < 32) {           // h0[k] (gates pre-transformed)
            float gi = sg0[tid];
            float gf = sg0[32 + tid];
            float gg = sg0[64 + tid];
            float go = sg0[96 + tid];
            c0 = gf * c0 + gi * gg;
            float hval = go * tanhf(c0);
            int d = (int)rank * 32 + tid;
            float* lp = ((float*)h0p[nb]) + hpad(d >> 2) * 4 + (d & 3);
            lp[0] = hval;                                   // local store
            #pragma unroll
            for (unsigned r = 1; r < 4; r++) cl_store_f32(lp, (rank + r) & 3, hval);
        }
        if (tid >= 32 && tid < 64 && k >= 1) {  // h1[k-1]
            int i = tid - 32;
            float gi = sg1[i];
            float gf = sg1[32 + i];
            float gg = sg1[64 + i];
            float go = sg1[96 + i];
            c1 = gf * c1 + gi * gg;
            float hval = go * tanhf(c1);
            int d = (int)rank * 32 + i;
            float* lp = ((float*)h1p[nb]) + hpad(d >> 2) * 4 + (d & 3);
            lp[0] = hval;
            #pragma unroll
            for (unsigned r = 1; r < 4; r++) cl_store_f32(lp, (rank + r) & 3, hval);
        }
        __syncthreads();   // local h visible to next phase's pre-wait compute
        cl_arrive();       // release remote stores; wait happens next iteration
    }
    cl_wait();             // consume the final arrive: h1[31] visible everywhere

    if (rank == 0) {                       // final projection (h1[31] in h1p[1])
        float v = 0.f;
        if (tid < 128) {
            v = ((float*)h1p[1])[hpad(tid >> 2) * 4 + (tid & 3)] * Wlin[tid];
            sg0[tid] = v;
        }
        __syncthreads();
        if (tid < 32) {
            float s = sg0[tid] + sg0[tid + 32] + sg0[tid + 64] + sg0[tid + 96];
            #pragma unroll
            for (int off = 16; off; off >>= 1) s += __shfl_xor_sync(0xffffffffu, s, off);
            if (tid == 0) out[batch] = s + blin[0];
        }
    }
    cl_sync();   // no CTA exits while peers may still target its smem
}

// ---------------- launch ----------------
extern "C" void kernel_launch(void* const* d_in, const int* in_sizes, int n_in,
                              void* d_out, int out_size) {
    const float* x     = (const float*)d_in[0];
    const int*   ei    = (const int*)d_in[1];
    const float* Wl1   = (const float*)d_in[2];
    const float* attl1 = (const float*)d_in[3];
    const float* attr1 = (const float*)d_in[4];
    const float* b1    = (const float*)d_in[5];
    const float* Wl2   = (const float*)d_in[6];
    const float* attl2 = (const float*)d_in[7];
    const float* attr2 = (const float*)d_in[8];
    const float* b2    = (const float*)d_in[9];
    const float* Wih0  = (const float*)d_in[10];
    const float* Whh0  = (const float*)d_in[11];
    const float* bih0  = (const float*)d_in[12];
    const float* bhh0  = (const float*)d_in[13];
    const float* Wih1  = (const float*)d_in[14];
    const float* Whh1  = (const float*)d_in[15];
    const float* bih1  = (const float*)d_in[16];
    const float* bhh1  = (const float*)d_in[17];
    const float* Wlin  = (const float*)d_in[18];
    const float* blin  = (const float*)d_in[19];
    float* out = (float*)d_out;

    k_pass1<<<dim3(64, T_STEPS), 256>>>(ei);
    k_pass2<<<dim3(64, T_STEPS), 256>>>(ei);
    k_gat1<<<dim3(MAX_SLOTS, T_STEPS), HID>>>(x, Wl1, attl1, attr1, b1, Wl2,
                                              attl2, attr2, b2);
    k_lstm_cl<<<128, 512>>>(Wih0, Whh0, bih0, bhh0,
                            Wih1, Whh1, bih1, bhh1, Wlin, blin, out);
}

// round 14
// speedup vs baseline: 1.1329x; 1.0374x over previous
#include <cuda_runtime.h>
#include <math.h>
#include <stdint.h>

#define T_STEPS 64
#define NN 16384
#define NE 262144
#define F_IN 8
#define H1 12
#define C1 16
#define HID 192
#define CAP0 256
#define MAX_SLOTS 48
#define CAPE 4096
#define LOCAL_CAP 128

// ---------------- scratch (static device globals; zero-initialized at load) ----------------
__device__ int   g_cnt0[T_STEPS];
__device__ int   g_e0[T_STEPS][CAP0];     // raw (atomic order) from pass1
__device__ int   g_s0[T_STEPS][CAP0];
__device__ int   g_e0s[T_STEPS][CAP0];    // canonical sorted copies (written by pass2 block0)
__device__ int   g_s0s[T_STEPS][CAP0];
__device__ int   g_slot0[T_STEPS][CAP0];
__device__ int   g_n0[T_STEPS];
__device__ int   g_scnt[T_STEPS];
__device__ int   g_S[T_STEPS][MAX_SLOTS];
__device__ int   g_incnt[T_STEPS];
__device__ int   g_ie_e[T_STEPS][CAPE];
__device__ int   g_ie_src[T_STEPS][CAPE];
__device__ int   g_ie_dst[T_STEPS][CAPE];
__device__ float g_xl2[T_STEPS][MAX_SLOTS];
__device__ float g_series[T_STEPS];
__device__ int   g_done3[T_STEPS];

__device__ __forceinline__ float lrelu(float x) { return x > 0.f ? x : 0.2f * x; }
__device__ __forceinline__ float sigm(float x) { return 1.f / (1.f + expf(-x)); }

// ---- packed fp32x2 FMA (sm_103a) ----
typedef unsigned long long ull;
__device__ __forceinline__ void fma2(ull& acc, ull w, ull h) {
    asm("fma.rn.f32x2 %0, %1, %2, %0;" : "+l"(acc) : "l"(w), "l"(h));
}
__device__ __forceinline__ ull pk2(float x, float y) {
    ull r; asm("mov.b64 %0, {%1, %2};" : "=l"(r) : "f"(x), "f"(y)); return r;
}
__device__ __forceinline__ float upksum(ull a) {
    float x, y; asm("mov.b64 {%0, %1}, %2;" : "=f"(x), "=f"(y) : "l"(a)); return x + y;
}

__device__ __forceinline__ void gdc_launch_dependents() {
    asm volatile("griddepcontrol.launch_dependents;");
}
__device__ __forceinline__ void gdc_wait() {
    asm volatile("griddepcontrol.wait;" ::: "memory");
}

__device__ __forceinline__ void edit_factor(int e, float& mul, float& add) {
    mul = 1.f; add = 0.f;
    if (e >= 0 && e < 23) {
        switch (e) {
            case 1: case 2: case 12: case 17: case 19: case 22: mul = 0.9f; break;
            case 7: case 14: mul = 0.9f; add = 0.1f; break;
            case 10: case 13: mul = 0.9f; add = 0.05f; break;
            default: break;
        }
    }
}

// ------------- K1: find edges with dst == 0 (16 vals/thread, min-tree) -------------
__global__ void k_pass1(const int* __restrict__ ei) {
    gdc_launch_dependents();
    const int t = blockIdx.y;
    const int* __restrict__ src = ei + (size_t)t * 2 * NE;
    const int* __restrict__ dst = src + NE;
    const int e0 = blockIdx.x * (256 * 16) + threadIdx.x * 16;
    int4 v0 = *(const int4*)(dst + e0);
    int4 v1 = *(const int4*)(dst + e0 + 4);
    int4 v2 = *(const int4*)(dst + e0 + 8);
    int4 v3 = *(const int4*)(dst + e0 + 12);
    int m0 = min(min(v0.x, v0.y), min(v0.z, v0.w));
    int m1 = min(min(v1.x, v1.y), min(v1.z, v1.w));
    int m2 = min(min(v2.x, v2.y), min(v2.z, v2.w));
    int m3 = min(min(v3.x, v3.y), min(v3.z, v3.w));
    if (min(min(m0, m1), min(m2, m3)) == 0) {
        int vals[16] = { v0.x, v0.y, v0.z, v0.w, v1.x, v1.y, v1.z, v1.w,
                         v2.x, v2.y, v2.z, v2.w, v3.x, v3.y, v3.z, v3.w };
        #pragma unroll
        for (int k = 0; k < 16; k++) {
            if (vals[k] == 0) {
                int p = atomicAdd(&g_cnt0[t], 1);
                if (p < CAP0) { g_e0[t][p] = e0 + k; g_s0[t][p] = src[e0 + k]; }
            }
        }
    }
}

// -- K2: edges into frontier set (page filter + byte-map; canonical build merged in) --
__global__ void k_pass2(const int* __restrict__ ei) {
    __shared__ unsigned char bmap[NN];   // 16 KB membership byte map
    __shared__ unsigned pagef[2];        // 64-bit page filter (256-node pages)
    gdc_launch_dependents();
    const int t = blockIdx.y;
    {   // pre-wait: zero bitmap (independent of pass1)
        int4* bm4 = (int4*)bmap;
        int4 z = make_int4(0, 0, 0, 0);
        for (int i = threadIdx.x; i < NN / 16; i += 256) bm4[i] = z;
    }
    if (threadIdx.x < 2) pagef[threadIdx.x] = 0;
    __syncthreads();

    gdc_wait();                          // pass1 grid complete; its writes visible

    int n = g_cnt0[t]; if (n > CAP0) n = CAP0;
    if (threadIdx.x < n) {
        int s = g_s0[t][threadIdx.x];
        bmap[s] = 1;
        unsigned pg = (unsigned)s >> 8;
        atomicOr(&pagef[pg >> 5], 1u << (pg & 31));
    }
    if (threadIdx.x == 0) {               // node 0 itself
        bmap[0] = 1;
        atomicOr(&pagef[0], 1u);
    }

    // block x==0, thread 0: build canonical sorted structures (separate arrays -> no race)
    if (blockIdx.x == 0 && threadIdx.x == 0) {
        int le[CAP0], ls[CAP0];
        for (int i = 0; i < n; i++) { le[i] = g_e0[t][i]; ls[i] = g_s0[t][i]; }
        for (int i = 1; i < n; i++) {
            int ke = le[i], ks = ls[i], j = i - 1;
            while (j >= 0 && le[j] > ke) { le[j + 1] = le[j]; ls[j + 1] = ls[j]; j--; }
            le[j + 1] = ke; ls[j + 1] = ks;
        }
        int sc = 1;
        g_S[t][0] = 0;
        for (int i = 0; i < n; i++) {
            int s = ls[i], slot = -1;
            for (int j = 0; j < sc; j++) if (g_S[t][j] == s) { slot = j; break; }
            if (slot < 0 && sc < MAX_SLOTS) { g_S[t][sc] = s; slot = sc; sc++; }
            g_slot0[t][i] = slot;
            g_e0s[t][i] = le[i]; g_s0s[t][i] = ls[i];
        }
        g_scnt[t] = sc;
        g_n0[t] = n;
    }
    __syncthreads();
    const unsigned pf0 = pagef[0], pf1 = pagef[1];

    const int* __restrict__ src = ei + (size_t)t * 2 * NE;
    const int* __restrict__ dst = src + NE;
    const int e0 = blockIdx.x * (256 * 16) + threadIdx.x * 16;
    int4 v0 = *(const int4*)(dst + e0);
    int4 v1 = *(const int4*)(dst + e0 + 4);
    int4 v2 = *(const int4*)(dst + e0 + 8);
    int4 v3 = *(const int4*)(dst + e0 + 12);
    int vals[16] = { v0.x, v0.y, v0.z, v0.w, v1.x, v1.y, v1.z, v1.w,
                     v2.x, v2.y, v2.z, v2.w, v3.x, v3.y, v3.z, v3.w };
    #pragma unroll
    for (int k = 0; k < 16; k++) {
        int d = vals[k];
        unsigned pg = (unsigned)d >> 8;
        unsigned w = (pg >= 32) ? pf1 : pf0;
        if ((w >> (pg & 31)) & 1u) {
            if (bmap[d]) {
                int p = atomicAdd(&g_incnt[t], 1);
                if (p < CAPE) { g_ie_e[t][p] = e0 + k; g_ie_src[t][p] = src[e0 + k]; g_ie_dst[t][p] = d; }
            }
        }
    }
}

// ==== K3: GAT layer 1 at frontier nodes (+ fused layer-2 in last-finishing block) ====
__global__ void k_gat1(const float* __restrict__ x, const float* __restrict__ Wl1,
                       const float* __restrict__ attl1, const float* __restrict__ attr1,
                       const float* __restrict__ b1, const float* __restrict__ Wl2,
                       const float* __restrict__ attl2, const float* __restrict__ attr2,
                       const float* __restrict__ b2) {
    gdc_launch_dependents();
    int t = blockIdx.y;
    int slot = blockIdx.x;
    int tid = threadIdx.x;              // 192 threads

    __shared__ float sWl[F_IN * HID];
    __shared__ float sAl[HID], sAr[HID], sB[HID], sW2[HID];
    __shared__ int   se[LOCAL_CAP], ss[LOCAL_CAP];
    __shared__ float sxr[LOCAL_CAP][F_IN];
    __shared__ float sal[LOCAL_CAP][H1];
    __shared__ float sm_[H1], sden[H1], sarU[H1];
    __shared__ float sfmul[LOCAL_CAP], sfadd[LOCAL_CAP];
    __shared__ float sred[HID];
    __shared__ int   sdeg;
    __shared__ int   sLast;
    __shared__ float l2xs[CAP0 + 1], l2a[CAP0 + 1];

    gdc_wait();                          // pass2 grid complete

    const int active = (slot < g_scnt[t]);
    if (active) {
        int u = g_S[t][slot];
        int h = tid >> 4, c = tid & 15;

        for (int i = tid; i < F_IN * HID; i += HID) sWl[i] = Wl1[i];
        sAl[tid] = attl1[tid]; sAr[tid] = attr1[tid]; sB[tid] = b1[tid]; sW2[tid] = Wl2[tid];
        if (tid == 0) sdeg = 0;
        __syncthreads();

        int cnt = g_incnt[t]; if (cnt > CAPE) cnt = CAPE;
        for (int i = tid; i < cnt; i += HID) {
            if (g_ie_dst[t][i] == u) {
                int p = atomicAdd(&sdeg, 1);
                if (p < LOCAL_CAP - 1) { se[p] = g_ie_e[t][i]; ss[p] = g_ie_src[t][i]; }
            }
        }
        __syncthreads();
        int deg = sdeg; if (deg > LOCAL_CAP - 1) deg = LOCAL_CAP - 1;
        if (tid == 0) {
            for (int i = 1; i < deg; i++) {                 // canonical order
                int ke = se[i], ks = ss[i], j = i - 1;
                while (j >= 0 && se[j] > ke) { se[j + 1] = se[j]; ss[j + 1] = ss[j]; j--; }
                se[j + 1] = ke; ss[j + 1] = ks;
            }
            se[deg] = 0x7fffffff; ss[deg] = u;              // self-loop last (never edited)
        }
        __syncthreads();
        int ndeg = deg + 1;

        for (int i = tid; i < ndeg * F_IN; i += HID)
            sxr[i >> 3][i & 7] = x[((size_t)t * NN + ss[i >> 3]) * F_IN + (i & 7)];
        __syncthreads();

        {   // ar_u from xl1[u] (self row at index deg)
            float v = 0.f;
            #pragma unroll
            for (int k = 0; k < F_IN; k++) v += sxr[deg][k] * sWl[k * HID + tid];
            float r = v * sAr[tid];
            #pragma unroll
            for (int off = 8; off; off >>= 1) r += __shfl_xor_sync(0xffffffffu, r, off, 16);
            if (c == 0) sarU[h] = r;
        }
        for (int i = 0; i < ndeg; i++) {
            float v = 0.f;
            #pragma unroll
            for (int k = 0; k < F_IN; k++) v += sxr[i][k] * sWl[k * HID + tid];
            float a = v * sAl[tid];
            #pragma unroll
            for (int off = 8; off; off >>= 1) a += __shfl_xor_sync(0xffffffffu, a, off, 16);
            if (c == 0) sal[i][h] = a;
        }
        __syncthreads();

        if (tid < H1) {
            int hh = tid;
            float m = -1e30f;
            for (int i = 0; i < ndeg; i++) { float a = lrelu(sal[i][hh] + sarU[hh]); if (a > m) m = a; }
            float den = 0.f;
            for (int i = 0; i < ndeg; i++) den += expf(lrelu(sal[i][hh] + sarU[hh]) - m);
            sm_[hh] = m; sden[hh] = den + 1e-16f;
        }
        if (tid >= 32 && tid < 32 + ndeg) {
            int i = tid - 32; float mu, ad; edit_factor(se[i], mu, ad); sfmul[i] = mu; sfadd[i] = ad;
        }
        __syncthreads();

        float acc = 0.f;
        for (int i = 0; i < ndeg; i++) {
            float a = lrelu(sal[i][h] + sarU[h]);
            float alpha = expf(a - sm_[h]) / sden[h];
            alpha = sfmul[i] * alpha + sfadd[i];
            float v = 0.f;
            #pragma unroll
            for (int k = 0; k < F_IN; k++) v += sxr[i][k] * sWl[k * HID + tid];
            acc += alpha * v;
        }
        acc += sB[tid];
        float e1 = acc > 0.f ? acc : (expf(acc) - 1.f);      // ELU
        sred[tid] = e1 * sW2[tid];
        __syncthreads();
        if (tid < 64) sred[tid] = sred[tid] + sred[tid + 64] + sred[tid + 128];
        __syncthreads();
        if (tid < 32) {
            float v = sred[tid] + sred[tid + 32];
            #pragma unroll
            for (int off = 16; off; off >>= 1) v += __shfl_xor_sync(0xffffffffu, v, off);
            if (tid == 0) g_xl2[t][slot] = v;
        }
    }

    // -------- completion counter; last block of this t runs GAT layer 2 --------
    __syncthreads();
    if (tid == 0) {
        __threadfence();
        int old = atomicAdd(&g_done3[t], 1);
        sLast = (old == gridDim.x - 1) ? 1 : 0;
        if (sLast) __threadfence();
    }
    __syncthreads();
    if (sLast) {
        int n = g_n0[t];
        if (tid < 32) {
            float al2 = attl2[0], ar2v = attr2[0];
            float x0 = *(volatile float*)&g_xl2[t][0];
            float ar0 = x0 * ar2v;
            float m = -1e30f;
            for (int i = tid; i <= n; i += 32) {
                float xs = (i < n) ? *(volatile float*)&g_xl2[t][g_slot0[t][i]] : x0;
                float a = lrelu(xs * al2 + ar0);
                l2xs[i] = xs; l2a[i] = a;
                m = fmaxf(m, a);
            }
            __syncwarp();
            #pragma unroll
            for (int off = 16; off; off >>= 1) m = fmaxf(m, __shfl_xor_sync(0xffffffffu, m, off));
            float den = 0.f;
            for (int i = tid; i <= n; i += 32) den += expf(l2a[i] - m);
            #pragma unroll
            for (int off = 16; off; off >>= 1) den += __shfl_xor_sync(0xffffffffu, den, off);
            den += 1e-16f;
            float outv = 0.f;
            for (int i = tid; i <= n; i += 32) {
                float alpha = expf(l2a[i] - m) / den;
                int e = (i < n) ? g_e0s[t][i] : 0x7fffffff;
                float mu, ad; edit_factor(e, mu, ad);
                outv += (mu * alpha + ad) * l2xs[i];
            }
            #pragma unroll
            for (int off = 16; off; off >>= 1) outv += __shfl_xor_sync(0xffffffffu, outv, off);
            if (tid == 0) {
                g_series[t] = outv + b2[0];
                g_cnt0[t] = 0; g_incnt[t] = 0; g_done3[t] = 0;   // reset for next replay
            }
        }
    }
}

// ========= K4: cluster-4 LSTM, reg weights (preloaded pre-wait), cluster.sync =========
__device__ __forceinline__ int hpad(int k4) { return k4 + (k4 >> 3); }
__device__ __forceinline__ unsigned cl_rank() {
    unsigned r; asm("mov.u32 %0, %%cluster_ctarank;" : "=r"(r)); return r;
}
__device__ __forceinline__ void cl_sync() {
    asm volatile("barrier.cluster.arrive.aligned;\n\tbarrier.cluster.wait.aligned;" ::: "memory");
}
__device__ __forceinline__ void cl_store_f32(float* p, unsigned rank, float v) {
    uint32_t a = (uint32_t)__cvta_generic_to_shared(p);
    uint32_t pa;
    asm("mapa.shared::cluster.u32 %0, %1, %2;" : "=r"(pa) : "r"(a), "r"(rank));
    asm volatile("st.shared::cluster.f32 [%0], %1;" :: "r"(pa), "f"(v) : "memory");
}

__global__ void __cluster_dims__(4, 1, 1) __launch_bounds__(512, 1)
k_lstm_cl(const float* __restrict__ Wih0, const float* __restrict__ Whh0,
          const float* __restrict__ bih0, const float* __restrict__ bhh0,
          const float* __restrict__ Wih1, const float* __restrict__ Whh1,
          const float* __restrict__ bih1, const float* __restrict__ bhh1,
          const float* __restrict__ Wlin, const float* __restrict__ blin,
          float* __restrict__ out) {
    __shared__ __align__(16) float4 h0p[2][36];
    __shared__ __align__(16) float4 h1p[2][36];
    __shared__ float sg0[128], sg1[128];
    __shared__ float xs[32];

    const unsigned rank = cl_rank();
    const int batch = blockIdx.x >> 2;
    const int tid = threadIdx.x;
    const int lr = tid >> 2, q = tid & 3;            // row 0..127, k-quarter
    const int gt = lr >> 5, dl = lr & 31;
    const int gr = gt * 128 + (int)rank * 32 + dl;   // global gate row

    // ---- pre-wait: weights -> registers (independent of gat1 output) ----
    ull w0p[16], w1p[32];
    {
        const float4* W0 = (const float4*)(Whh0 + (size_t)gr * 128) + 8 * q;
        #pragma unroll
        for (int j = 0; j < 8; j++) {
            float4 w = W0[j];
            w0p[2 * j] = pk2(w.x, w.y); w0p[2 * j + 1] = pk2(w.z, w.w);
        }
        const float* Wsrc = (q < 2) ? Wih1 : Whh1;
        const float4* W1 = (const float4*)(Wsrc + (size_t)gr * 128) + 16 * (q & 1);
        #pragma unroll
        for (int j = 0; j < 16; j++) {
            float4 w = W1[j];
            w1p[2 * j] = pk2(w.x, w.y); w1p[2 * j + 1] = pk2(w.z, w.w);
        }
    }
    float wih0v = 0.f, bA = 0.f, bB = 0.f;
    if (q == 0) { wih0v = Wih0[gr]; bA = bih0[gr] + bhh0[gr]; bB = bih1[gr] + bhh1[gr]; }
    {
        float* hz = (float*)&h0p[0][0];
        for (int i = tid; i < 2 * 2 * 36 * 4; i += 512) hz[i] = 0.f;
    }

    gdc_wait();                          // gat1 grid complete; g_series visible
    if (tid < 32) xs[tid] = g_series[batch + tid];

    float c0 = 0.f, c1 = 0.f;
    const int hb = 16 * (q & 1);
    cl_sync();

    for (int k = 0; k <= 32; k++) {
        const int pb = k & 1, nb = pb ^ 1;
        if (k < 32) {                     // gates0 for step k (reads h0[k-1])
            const float4* hv = h0p[pb];
            ull a0 = 0ull, a1 = 0ull;
            #pragma unroll
            for (int j = 0; j < 8; j += 2) {
                float4 ha = hv[hpad(8 * q + j)];
                float4 hbv = hv[hpad(8 * q + j + 1)];
                fma2(a0, w0p[2 * j],     *(ull*)&ha.x);
                fma2(a1, w0p[2 * j + 1], *(ull*)&ha.z);
                fma2(a0, w0p[2 * j + 2], *(ull*)&hbv.x);
                fma2(a1, w0p[2 * j + 3], *(ull*)&hbv.z);
            }
            float acc = upksum(a0) + upksum(a1);
            acc += __shfl_xor_sync(0xffffffffu, acc, 1, 4);
            acc += __shfl_xor_sync(0xffffffffu, acc, 2, 4);
            if (q == 0) {
                float gv = acc + bA + wih0v * xs[k];
                sg0[lr] = (gt == 2) ? tanhf(gv) : sigm(gv);   // producer-side nonlinearity
            }
        }
        if (k >= 1) {                     // gates1 for step k-1 (reads h0[k-1], h1[k-2])
            const float4* hsrc = (q < 2) ? h0p[pb] : h1p[pb];
            ull a0 = 0ull, a1 = 0ull;
            #pragma unroll
            for (int j = 0; j < 16; j += 2) {
                float4 ha = hsrc[hpad(hb + j)];
                float4 hbv = hsrc[hpad(hb + j + 1)];
                fma2(a0, w1p[2 * j],     *(ull*)&ha.x);
                fma2(a1, w1p[2 * j + 1], *(ull*)&ha.z);
                fma2(a0, w1p[2 * j + 2], *(ull*)&hbv.x);
                fma2(a1, w1p[2 * j + 3], *(ull*)&hbv.z);
            }
            float acc = upksum(a0) + upksum(a1);
            acc += __shfl_xor_sync(0xffffffffu, acc, 1, 4);
            acc += __shfl_xor_sync(0xffffffffu, acc, 2, 4);
            if (q == 0) {
                float gv = acc + bB;
                sg1[lr] = (gt == 2) ? tanhf(gv) : sigm(gv);
            }
        }
        __syncthreads();
        if (tid < 32 && k < 32) {           // h0[k] (gates pre-transformed)
            float gi = sg0[tid];
            float gf = sg0[32 + tid];
            float gg = sg0[64 + tid];
            float go = sg0[96 + tid];
            c0 = gf * c0 + gi * gg;
            float hval = go * tanhf(c0);
            int d = (int)rank * 32 + tid;
            float* lp = ((float*)h0p[nb]) + hpad(d >> 2) * 4 + (d & 3);
            lp[0] = hval;                                   // local store
            #pragma unroll
            for (unsigned r = 1; r < 4; r++) cl_store_f32(lp, (rank + r) & 3, hval);
        }
        if (tid >= 32 && tid < 64 && k >= 1) {  // h1[k-1]
            int i = tid - 32;
            float gi = sg1[i];
            float gf = sg1[32 + i];
            float gg = sg1[64 + i];
            float go = sg1[96 + i];
            c1 = gf * c1 + gi * gg;
            float hval = go * tanhf(c1);
            int d = (int)rank * 32 + i;
            float* lp = ((float*)h1p[nb]) + hpad(d >> 2) * 4 + (d & 3);
            lp[0] = hval;
            #pragma unroll
            for (unsigned r = 1; r < 4; r++) cl_store_f32(lp, (rank + r) & 3, hval);
        }
        cl_sync();
    }

    if (rank == 0) {                       // final projection (h1[31] in h1p[1])
        float v = 0.f;
        if (tid < 128) {
            v = ((float*)h1p[1])[hpad(tid >> 2) * 4 + (tid & 3)] * Wlin[tid];
            sg0[tid] = v;
        }
        __syncthreads();
        if (tid < 32) {
            float s = sg0[tid] + sg0[tid + 32] + sg0[tid + 64] + sg0[tid + 96];
            #pragma unroll
            for (int off = 16; off; off >>= 1) s += __shfl_xor_sync(0xffffffffu, s, off);
            if (tid == 0) out[batch] = s + blin[0];
        }
    }
    cl_sync();   // no CTA exits while peers may still target its smem
}

// ---------------- launch ----------------
static void launch_pdl(const void* fn, dim3 grid, dim3 block, void** args,
                       int cluster = 0) {
    cudaLaunchConfig_t cfg = {};
    cfg.gridDim = grid;
    cfg.blockDim = block;
    cfg.dynamicSmemBytes = 0;
    cfg.stream = 0;
    cudaLaunchAttribute attrs[2];
    attrs[0].id = cudaLaunchAttributeProgrammaticStreamSerialization;
    attrs[0].val.programmaticStreamSerializationAllowed = 1;
    int na = 1;
    if (cluster) {
        attrs[1].id = cudaLaunchAttributeClusterDimension;
        attrs[1].val.clusterDim.x = cluster;
        attrs[1].val.clusterDim.y = 1;
        attrs[1].val.clusterDim.z = 1;
        na = 2;
    }
    cfg.attrs = attrs;
    cfg.numAttrs = na;
    cudaLaunchKernelExC(&cfg, fn, args);
}

extern "C" void kernel_launch(void* const* d_in, const int* in_sizes, int n_in,
                              void* d_out, int out_size) {
    const float* x     = (const float*)d_in[0];
    const int*   ei    = (const int*)d_in[1];
    const float* Wl1   = (const float*)d_in[2];
    const float* attl1 = (const float*)d_in[3];
    const float* attr1 = (const float*)d_in[4];
    const float* b1    = (const float*)d_in[5];
    const float* Wl2   = (const float*)d_in[6];
    const float* attl2 = (const float*)d_in[7];
    const float* attr2 = (const float*)d_in[8];
    const float* b2    = (const float*)d_in[9];
    const float* Wih0  = (const float*)d_in[10];
    const float* Whh0  = (const float*)d_in[11];
    const float* bih0  = (const float*)d_in[12];
    const float* bhh0  = (const float*)d_in[13];
    const float* Wih1  = (const float*)d_in[14];
    const float* Whh1  = (const float*)d_in[15];
    const float* bih1  = (const float*)d_in[16];
    const float* bhh1  = (const float*)d_in[17];
    const float* Wlin  = (const float*)d_in[18];
    const float* blin  = (const float*)d_in[19];
    float* out = (float*)d_out;

    k_pass1<<<dim3(64, T_STEPS), 256>>>(ei);

    {
        void* args[] = { (void*)&ei };
        launch_pdl((const void*)k_pass2, dim3(64, T_STEPS), dim3(256), args);
    }
    {
        void* args[] = { (void*)&x, (void*)&Wl1, (void*)&attl1, (void*)&attr1,
                         (void*)&b1, (void*)&Wl2, (void*)&attl2, (void*)&attr2,
                         (void*)&b2 };
        launch_pdl((const void*)k_gat1, dim3(MAX_SLOTS, T_STEPS), dim3(HID), args);
    }
    {
        void* args[] = { (void*)&Wih0, (void*)&Whh0, (void*)&bih0, (void*)&bhh0,
                         (void*)&Wih1, (void*)&Whh1, (void*)&bih1, (void*)&bhh1,
                         (void*)&Wlin, (void*)&blin, (void*)&out };
        launch_pdl((const void*)k_lstm_cl, dim3(128), dim3(512), args, 4);
    }
}

// round 15
// speedup vs baseline: 1.1335x; 1.0006x over previous
#include <cuda_runtime.h>
#include <math.h>
#include <stdint.h>

#define T_STEPS 64
#define NN 16384
#define NE 262144
#define F_IN 8
#define H1 12
#define C1 16
#define HID 192
#define CAP0 256
#define MAX_SLOTS 48
#define CAPE 4096
#define LOCAL_CAP 128

// ---------------- scratch (static device globals; zero-initialized at load) ----------------
__device__ int   g_cnt0[T_STEPS];
__device__ int   g_e0[T_STEPS][CAP0];     // raw (atomic order) from pass1
__device__ int   g_s0[T_STEPS][CAP0];
__device__ int   g_e0s[T_STEPS][CAP0];    // canonical sorted copies (written by pass2 block0)
__device__ int   g_s0s[T_STEPS][CAP0];
__device__ int   g_slot0[T_STEPS][CAP0];
__device__ int   g_n0[T_STEPS];
__device__ int   g_scnt[T_STEPS];
__device__ int   g_S[T_STEPS][MAX_SLOTS];
__device__ int   g_incnt[T_STEPS];
__device__ int   g_ie_e[T_STEPS][CAPE];
__device__ int   g_ie_src[T_STEPS][CAPE];
__device__ int   g_ie_dst[T_STEPS][CAPE];
__device__ float g_xl2[T_STEPS][MAX_SLOTS];
__device__ float g_series[T_STEPS];
__device__ int   g_done3[T_STEPS];

__device__ __forceinline__ float lrelu(float x) { return x > 0.f ? x : 0.2f * x; }
__device__ __forceinline__ float sigm(float x) { return 1.f / (1.f + expf(-x)); }

// ---- packed fp32x2 FMA (sm_103a) ----
typedef unsigned long long ull;
__device__ __forceinline__ void fma2(ull& acc, ull w, ull h) {
    asm("fma.rn.f32x2 %0, %1, %2, %0;" : "+l"(acc) : "l"(w), "l"(h));
}
__device__ __forceinline__ ull pk2(float x, float y) {
    ull r; asm("mov.b64 %0, {%1, %2};" : "=l"(r) : "f"(x), "f"(y)); return r;
}
__device__ __forceinline__ float upksum(ull a) {
    float x, y; asm("mov.b64 {%0, %1}, %2;" : "=f"(x), "=f"(y) : "l"(a)); return x + y;
}

__device__ __forceinline__ void gdc_launch_dependents() {
    asm volatile("griddepcontrol.launch_dependents;");
}
__device__ __forceinline__ void gdc_wait() {
    asm volatile("griddepcontrol.wait;" ::: "memory");
}

__device__ __forceinline__ void edit_factor(int e, float& mul, float& add) {
    mul = 1.f; add = 0.f;
    if (e >= 0 && e < 23) {
        switch (e) {
            case 1: case 2: case 12: case 17: case 19: case 22: mul = 0.9f; break;
            case 7: case 14: mul = 0.9f; add = 0.1f; break;
            case 10: case 13: mul = 0.9f; add = 0.05f; break;
            default: break;
        }
    }
}

// ------------- K1: find edges with dst == 0 (16 vals/thread, min-tree) -------------
__global__ void k_pass1(const int* __restrict__ ei) {
    gdc_launch_dependents();
    const int t = blockIdx.y;
    const int* __restrict__ src = ei + (size_t)t * 2 * NE;
    const int* __restrict__ dst = src + NE;
    const int e0 = blockIdx.x * (256 * 16) + threadIdx.x * 16;
    int4 v0 = *(const int4*)(dst + e0);
    int4 v1 = *(const int4*)(dst + e0 + 4);
    int4 v2 = *(const int4*)(dst + e0 + 8);
    int4 v3 = *(const int4*)(dst + e0 + 12);
    int m0 = min(min(v0.x, v0.y), min(v0.z, v0.w));
    int m1 = min(min(v1.x, v1.y), min(v1.z, v1.w));
    int m2 = min(min(v2.x, v2.y), min(v2.z, v2.w));
    int m3 = min(min(v3.x, v3.y), min(v3.z, v3.w));
    if (min(min(m0, m1), min(m2, m3)) == 0) {
        int vals[16] = { v0.x, v0.y, v0.z, v0.w, v1.x, v1.y, v1.z, v1.w,
                         v2.x, v2.y, v2.z, v2.w, v3.x, v3.y, v3.z, v3.w };
        #pragma unroll
        for (int k = 0; k < 16; k++) {
            if (vals[k] == 0) {
                int p = atomicAdd(&g_cnt0[t], 1);
                if (p < CAP0) { g_e0[t][p] = e0 + k; g_s0[t][p] = src[e0 + k]; }
            }
        }
    }
}

// -- K2: edges into frontier set (page filter + byte-map; canonical build merged in) --
__global__ void k_pass2(const int* __restrict__ ei) {
    __shared__ unsigned char bmap[NN];   // 16 KB membership byte map
    __shared__ unsigned pagef[2];        // 64-bit page filter (256-node pages)
    gdc_launch_dependents();
    const int t = blockIdx.y;
    {   // pre-wait: zero bitmap (independent of pass1)
        int4* bm4 = (int4*)bmap;
        int4 z = make_int4(0, 0, 0, 0);
        for (int i = threadIdx.x; i < NN / 16; i += 256) bm4[i] = z;
    }
    if (threadIdx.x < 2) pagef[threadIdx.x] = 0;
    __syncthreads();

    gdc_wait();                          // pass1 grid complete; its writes visible

    int n = g_cnt0[t]; if (n > CAP0) n = CAP0;
    if (threadIdx.x < n) {
        int s = g_s0[t][threadIdx.x];
        bmap[s] = 1;
        unsigned pg = (unsigned)s >> 8;
        atomicOr(&pagef[pg >> 5], 1u << (pg & 31));
    }
    if (threadIdx.x == 0) {               // node 0 itself
        bmap[0] = 1;
        atomicOr(&pagef[0], 1u);
    }

    // block x==0, thread 0: build canonical sorted structures (separate arrays -> no race)
    if (blockIdx.x == 0 && threadIdx.x == 0) {
        int le[CAP0], ls[CAP0];
        for (int i = 0; i < n; i++) { le[i] = g_e0[t][i]; ls[i] = g_s0[t][i]; }
        for (int i = 1; i < n; i++) {
            int ke = le[i], ks = ls[i], j = i - 1;
            while (j >= 0 && le[j] > ke) { le[j + 1] = le[j]; ls[j + 1] = ls[j]; j--; }
            le[j + 1] = ke; ls[j + 1] = ks;
        }
        int sc = 1;
        g_S[t][0] = 0;
        for (int i = 0; i < n; i++) {
            int s = ls[i], slot = -1;
            for (int j = 0; j < sc; j++) if (g_S[t][j] == s) { slot = j; break; }
            if (slot < 0 && sc < MAX_SLOTS) { g_S[t][sc] = s; slot = sc; sc++; }
            g_slot0[t][i] = slot;
            g_e0s[t][i] = le[i]; g_s0s[t][i] = ls[i];
        }
        g_scnt[t] = sc;
        g_n0[t] = n;
    }
    __syncthreads();
    const unsigned pf0 = pagef[0], pf1 = pagef[1];

    const int* __restrict__ src = ei + (size_t)t * 2 * NE;
    const int* __restrict__ dst = src + NE;
    const int e0 = blockIdx.x * (256 * 16) + threadIdx.x * 16;
    int4 v0 = *(const int4*)(dst + e0);
    int4 v1 = *(const int4*)(dst + e0 + 4);
    int4 v2 = *(const int4*)(dst + e0 + 8);
    int4 v3 = *(const int4*)(dst + e0 + 12);
    int vals[16] = { v0.x, v0.y, v0.z, v0.w, v1.x, v1.y, v1.z, v1.w,
                     v2.x, v2.y, v2.z, v2.w, v3.x, v3.y, v3.z, v3.w };
    #pragma unroll
    for (int k = 0; k < 16; k++) {
        int d = vals[k];
        unsigned pg = (unsigned)d >> 8;
        unsigned w = (pg >= 32) ? pf1 : pf0;
        if ((w >> (pg & 31)) & 1u) {
            if (bmap[d]) {
                int p = atomicAdd(&g_incnt[t], 1);
                if (p < CAPE) { g_ie_e[t][p] = e0 + k; g_ie_src[t][p] = src[e0 + k]; g_ie_dst[t][p] = d; }
            }
        }
    }
}

// ==== K3: GAT layer 1 at frontier nodes (+ fused layer-2 in last-finishing block) ====
__global__ void k_gat1(const float* __restrict__ x, const float* __restrict__ Wl1,
                       const float* __restrict__ attl1, const float* __restrict__ attr1,
                       const float* __restrict__ b1, const float* __restrict__ Wl2,
                       const float* __restrict__ attl2, const float* __restrict__ attr2,
                       const float* __restrict__ b2) {
    gdc_launch_dependents();
    int t = blockIdx.y;
    int slot = blockIdx.x;
    int tid = threadIdx.x;              // 192 threads

    __shared__ float sWl[F_IN * HID];
    __shared__ float sAl[HID], sAr[HID], sB[HID], sW2[HID];
    __shared__ int   se[LOCAL_CAP], ss[LOCAL_CAP];
    __shared__ float sxr[LOCAL_CAP][F_IN];
    __shared__ float sal[LOCAL_CAP][H1];
    __shared__ float sm_[H1], sden[H1], sarU[H1];
    __shared__ float sfmul[LOCAL_CAP], sfadd[LOCAL_CAP];
    __shared__ float sred[HID];
    __shared__ int   sdeg;
    __shared__ int   sLast;
    __shared__ float l2xs[CAP0 + 1], l2a[CAP0 + 1];

    gdc_wait();                          // pass2 grid complete

    const int active = (slot < g_scnt[t]);
    if (active) {
        int u = g_S[t][slot];
        int h = tid >> 4, c = tid & 15;

        for (int i = tid; i < F_IN * HID; i += HID) sWl[i] = Wl1[i];
        sAl[tid] = attl1[tid]; sAr[tid] = attr1[tid]; sB[tid] = b1[tid]; sW2[tid] = Wl2[tid];
        if (tid == 0) sdeg = 0;
        __syncthreads();

        int cnt = g_incnt[t]; if (cnt > CAPE) cnt = CAPE;
        for (int i = tid; i < cnt; i += HID) {
            if (g_ie_dst[t][i] == u) {
                int p = atomicAdd(&sdeg, 1);
                if (p < LOCAL_CAP - 1) { se[p] = g_ie_e[t][i]; ss[p] = g_ie_src[t][i]; }
            }
        }
        __syncthreads();
        int deg = sdeg; if (deg > LOCAL_CAP - 1) deg = LOCAL_CAP - 1;
        if (tid == 0) {
            for (int i = 1; i < deg; i++) {                 // canonical order
                int ke = se[i], ks = ss[i], j = i - 1;
                while (j >= 0 && se[j] > ke) { se[j + 1] = se[j]; ss[j + 1] = ss[j]; j--; }
                se[j + 1] = ke; ss[j + 1] = ks;
            }
            se[deg] = 0x7fffffff; ss[deg] = u;              // self-loop last (never edited)
        }
        __syncthreads();
        int ndeg = deg + 1;

        for (int i = tid; i < ndeg * F_IN; i += HID)
            sxr[i >> 3][i & 7] = x[((size_t)t * NN + ss[i >> 3]) * F_IN + (i & 7)];
        __syncthreads();

        {   // ar_u from xl1[u] (self row at index deg)
            float v = 0.f;
            #pragma unroll
            for (int k = 0; k < F_IN; k++) v += sxr[deg][k] * sWl[k * HID + tid];
            float r = v * sAr[tid];
            #pragma unroll
            for (int off = 8; off; off >>= 1) r += __shfl_xor_sync(0xffffffffu, r, off, 16);
            if (c == 0) sarU[h] = r;
        }
        for (int i = 0; i < ndeg; i++) {
            float v = 0.f;
            #pragma unroll
            for (int k = 0; k < F_IN; k++) v += sxr[i][k] * sWl[k * HID + tid];
            float a = v * sAl[tid];
            #pragma unroll
            for (int off = 8; off; off >>= 1) a += __shfl_xor_sync(0xffffffffu, a, off, 16);
            if (c == 0) sal[i][h] = a;
        }
        __syncthreads();

        if (tid < H1) {
            int hh = tid;
            float m = -1e30f;
            for (int i = 0; i < ndeg; i++) { float a = lrelu(sal[i][hh] + sarU[hh]); if (a > m) m = a; }
            float den = 0.f;
            for (int i = 0; i < ndeg; i++) den += expf(lrelu(sal[i][hh] + sarU[hh]) - m);
            sm_[hh] = m; sden[hh] = den + 1e-16f;
        }
        if (tid >= 32 && tid < 32 + ndeg) {
            int i = tid - 32; float mu, ad; edit_factor(se[i], mu, ad); sfmul[i] = mu; sfadd[i] = ad;
        }
        __syncthreads();

        float acc = 0.f;
        for (int i = 0; i < ndeg; i++) {
            float a = lrelu(sal[i][h] + sarU[h]);
            float alpha = expf(a - sm_[h]) / sden[h];
            alpha = sfmul[i] * alpha + sfadd[i];
            float v = 0.f;
            #pragma unroll
            for (int k = 0; k < F_IN; k++) v += sxr[i][k] * sWl[k * HID + tid];
            acc += alpha * v;
        }
        acc += sB[tid];
        float e1 = acc > 0.f ? acc : (expf(acc) - 1.f);      // ELU
        sred[tid] = e1 * sW2[tid];
        __syncthreads();
        if (tid < 64) sred[tid] = sred[tid] + sred[tid + 64] + sred[tid + 128];
        __syncthreads();
        if (tid < 32) {
            float v = sred[tid] + sred[tid + 32];
            #pragma unroll
            for (int off = 16; off; off >>= 1) v += __shfl_xor_sync(0xffffffffu, v, off);
            if (tid == 0) g_xl2[t][slot] = v;
        }
    }

    // -------- completion counter; last block of this t runs GAT layer 2 --------
    __syncthreads();
    if (tid == 0) {
        __threadfence();
        int old = atomicAdd(&g_done3[t], 1);
        sLast = (old == gridDim.x - 1) ? 1 : 0;
        if (sLast) __threadfence();
    }
    __syncthreads();
    if (sLast) {
        int n = g_n0[t];
        if (tid < 32) {
            float al2 = attl2[0], ar2v = attr2[0];
            float x0 = *(volatile float*)&g_xl2[t][0];
            float ar0 = x0 * ar2v;
            float m = -1e30f;
            for (int i = tid; i <= n; i += 32) {
                float xs = (i < n) ? *(volatile float*)&g_xl2[t][g_slot0[t][i]] : x0;
                float a = lrelu(xs * al2 + ar0);
                l2xs[i] = xs; l2a[i] = a;
                m = fmaxf(m, a);
            }
            __syncwarp();
            #pragma unroll
            for (int off = 16; off; off >>= 1) m = fmaxf(m, __shfl_xor_sync(0xffffffffu, m, off));
            float den = 0.f;
            for (int i = tid; i <= n; i += 32) den += expf(l2a[i] - m);
            #pragma unroll
            for (int off = 16; off; off >>= 1) den += __shfl_xor_sync(0xffffffffu, den, off);
            den += 1e-16f;
            float outv = 0.f;
            for (int i = tid; i <= n; i += 32) {
                float alpha = expf(l2a[i] - m) / den;
                int e = (i < n) ? g_e0s[t][i] : 0x7fffffff;
                float mu, ad; edit_factor(e, mu, ad);
                outv += (mu * alpha + ad) * l2xs[i];
            }
            #pragma unroll
            for (int off = 16; off; off >>= 1) outv += __shfl_xor_sync(0xffffffffu, outv, off);
            if (tid == 0) {
                g_series[t] = outv + b2[0];
                g_cnt0[t] = 0; g_incnt[t] = 0; g_done3[t] = 0;   // reset for next replay
            }
        }
    }
}

// ========= K4: cluster-4 LSTM, reg weights (preloaded pre-wait), cluster.sync =========
__device__ __forceinline__ int hpad(int k4) { return k4 + (k4 >> 3); }
__device__ __forceinline__ unsigned cl_rank() {
    unsigned r; asm("mov.u32 %0, %%cluster_ctarank;" : "=r"(r)); return r;
}
__device__ __forceinline__ void cl_sync() {
    asm volatile("barrier.cluster.arrive.aligned;\n\tbarrier.cluster.wait.aligned;" ::: "memory");
}
__device__ __forceinline__ void cl_store_f32(float* p, unsigned rank, float v) {
    uint32_t a = (uint32_t)__cvta_generic_to_shared(p);
    uint32_t pa;
    asm("mapa.shared::cluster.u32 %0, %1, %2;" : "=r"(pa) : "r"(a), "r"(rank));
    asm volatile("st.shared::cluster.f32 [%0], %1;" :: "r"(pa), "f"(v) : "memory");
}

__global__ void __cluster_dims__(4, 1, 1) __launch_bounds__(512, 1)
k_lstm_cl(const float* __restrict__ Wih0, const float* __restrict__ Whh0,
          const float* __restrict__ bih0, const float* __restrict__ bhh0,
          const float* __restrict__ Wih1, const float* __restrict__ Whh1,
          const float* __restrict__ bih1, const float* __restrict__ bhh1,
          const float* __restrict__ Wlin, const float* __restrict__ blin,
          float* __restrict__ out) {
    __shared__ __align__(16) float4 h0p[2][36];
    __shared__ __align__(16) float4 h1p[2][36];
    __shared__ float sg0[128], sg1[128];
    __shared__ float xs[32];

    const unsigned rank = cl_rank();
    const int batch = blockIdx.x >> 2;
    const int tid = threadIdx.x;
    const int lr = tid >> 2, q = tid & 3;            // row 0..127, k-quarter
    const int gt = lr >> 5, dl = lr & 31;
    const int gr = gt * 128 + (int)rank * 32 + dl;   // global gate row

    // ---- pre-wait: weights -> registers (independent of gat1 output) ----
    ull w0p[16], w1p[32];
    {
        const float4* W0 = (const float4*)(Whh0 + (size_t)gr * 128) + 8 * q;
        #pragma unroll
        for (int j = 0; j < 8; j++) {
            float4 w = W0[j];
            w0p[2 * j] = pk2(w.x, w.y); w0p[2 * j + 1] = pk2(w.z, w.w);
        }
        const float* Wsrc = (q < 2) ? Wih1 : Whh1;
        const float4* W1 = (const float4*)(Wsrc + (size_t)gr * 128) + 16 * (q & 1);
        #pragma unroll
        for (int j = 0; j < 16; j++) {
            float4 w = W1[j];
            w1p[2 * j] = pk2(w.x, w.y); w1p[2 * j + 1] = pk2(w.z, w.w);
        }
    }
    float wih0v = 0.f, bA = 0.f, bB = 0.f;
    if (q == 0) { wih0v = Wih0[gr]; bA = bih0[gr] + bhh0[gr]; bB = bih1[gr] + bhh1[gr]; }
    {
        float* hz = (float*)&h0p[0][0];
        for (int i = tid; i < 2 * 2 * 36 * 4; i += 512) hz[i] = 0.f;
    }

    gdc_wait();                          // gat1 grid complete; g_series visible
    if (tid < 32) xs[tid] = g_series[batch + tid];

    float c0 = 0.f, c1 = 0.f;
    const int hb = 16 * (q & 1);
    cl_sync();

    for (int k = 0; k <= 32; k++) {
        const int pb = k & 1, nb = pb ^ 1;
        if (k < 32) {                     // gates0 for step k (reads h0[k-1])
            const float4* hv = h0p[pb];
            ull a0 = 0ull, a1 = 0ull;
            #pragma unroll
            for (int j = 0; j < 8; j += 2) {
                float4 ha = hv[hpad(8 * q + j)];
                float4 hbv = hv[hpad(8 * q + j + 1)];
                fma2(a0, w0p[2 * j],     *(ull*)&ha.x);
                fma2(a1, w0p[2 * j + 1], *(ull*)&ha.z);
                fma2(a0, w0p[2 * j + 2], *(ull*)&hbv.x);
                fma2(a1, w0p[2 * j + 3], *(ull*)&hbv.z);
            }
            float acc = upksum(a0) + upksum(a1);
            acc += __shfl_xor_sync(0xffffffffu, acc, 1, 4);
            acc += __shfl_xor_sync(0xffffffffu, acc, 2, 4);
            if (q == 0) {
                float gv = acc + bA + wih0v * xs[k];
                sg0[lr] = (gt == 2) ? tanhf(gv) : sigm(gv);   // producer-side nonlinearity
            }
        }
        if (k >= 1) {                     // gates1 for step k-1 (reads h0[k-1], h1[k-2])
            const float4* hsrc = (q < 2) ? h0p[pb] : h1p[pb];
            ull a0 = 0ull, a1 = 0ull;
            #pragma unroll
            for (int j = 0; j < 16; j += 2) {
                float4 ha = hsrc[hpad(hb + j)];
                float4 hbv = hsrc[hpad(hb + j + 1)];
                fma2(a0, w1p[2 * j],     *(ull*)&ha.x);
                fma2(a1, w1p[2 * j + 1], *(ull*)&ha.z);
                fma2(a0, w1p[2 * j + 2], *(ull*)&hbv.x);
                fma2(a1, w1p[2 * j + 3], *(ull*)&hbv.z);
            }
            float acc = upksum(a0) + upksum(a1);
            acc += __shfl_xor_sync(0xffffffffu, acc, 1, 4);
            acc += __shfl_xor_sync(0xffffffffu, acc, 2, 4);
            if (q == 0) {
                float gv = acc + bB;
                sg1[lr] = (gt == 2) ? tanhf(gv) : sigm(gv);
            }
        }
        __syncthreads();
        if (tid < 32 && k < 32) {           // h0[k] (gates pre-transformed)
            float gi = sg0[tid];
            float gf = sg0[32 + tid];
            float gg = sg0[64 + tid];
            float go = sg0[96 + tid];
            c0 = gf * c0 + gi * gg;
            float hval = go * tanhf(c0);
            int d = (int)rank * 32 + tid;
            float* lp = ((float*)h0p[nb]) + hpad(d >> 2) * 4 + (d & 3);
            lp[0] = hval;                                   // local store
            #pragma unroll
            for (unsigned r = 1; r < 4; r++) cl_store_f32(lp, (rank + r) & 3, hval);
        }
        if (tid >= 32 && tid < 64 && k >= 1) {  // h1[k-1]
            int i = tid - 32;
            float gi = sg1[i];
            float gf = sg1[32 + i];
            float gg = sg1[64 + i];
            float go = sg1[96 + i];
            c1 = gf * c1 + gi * gg;
            float hval = go * tanhf(c1);
            int d = (int)rank * 32 + i;
            float* lp = ((float*)h1p[nb]) + hpad(d >> 2) * 4 + (d & 3);
            lp[0] = hval;
            #pragma unroll
            for (unsigned r = 1; r < 4; r++) cl_store_f32(lp, (rank + r) & 3, hval);
        }
        cl_sync();
    }

    if (rank == 0) {                       // final projection (h1[31] in h1p[1])
        float v = 0.f;
        if (tid < 128) {
            v = ((float*)h1p[1])[hpad(tid >> 2) * 4 + (tid & 3)] * Wlin[tid];
            sg0[tid] = v;
        }
        __syncthreads();
        if (tid < 32) {
            float s = sg0[tid] + sg0[tid + 32] + sg0[tid + 64] + sg0[tid + 96];
            #pragma unroll
            for (int off = 16; off; off >>= 1) s += __shfl_xor_sync(0xffffffffu, s, off);
            if (tid == 0) out[batch] = s + blin[0];
        }
    }
    cl_sync();   // no CTA exits while peers may still target its smem
}

// ---------------- launch ----------------
static void launch_pdl(const void* fn, dim3 grid, dim3 block, void** args,
                       int cluster = 0) {
    cudaLaunchConfig_t cfg = {};
    cfg.gridDim = grid;
    cfg.blockDim = block;
    cfg.dynamicSmemBytes = 0;
    cfg.stream = 0;
    cudaLaunchAttribute attrs[2];
    attrs[0].id = cudaLaunchAttributeProgrammaticStreamSerialization;
    attrs[0].val.programmaticStreamSerializationAllowed = 1;
    int na = 1;
    if (cluster) {
        attrs[1].id = cudaLaunchAttributeClusterDimension;
        attrs[1].val.clusterDim.x = cluster;
        attrs[1].val.clusterDim.y = 1;
        attrs[1].val.clusterDim.z = 1;
        na = 2;
    }
    cfg.attrs = attrs;
    cfg.numAttrs = na;
    cudaLaunchKernelExC(&cfg, fn, args);
}

extern "C" void kernel_launch(void* const* d_in, const int* in_sizes, int n_in,
                              void* d_out, int out_size) {
    const float* x     = (const float*)d_in[0];
    const int*   ei    = (const int*)d_in[1];
    const float* Wl1   = (const float*)d_in[2];
    const float* attl1 = (const float*)d_in[3];
    const float* attr1 = (const float*)d_in[4];
    const float* b1    = (const float*)d_in[5];
    const float* Wl2   = (const float*)d_in[6];
    const float* attl2 = (const float*)d_in[7];
    const float* attr2 = (const float*)d_in[8];
    const float* b2    = (const float*)d_in[9];
    const float* Wih0  = (const float*)d_in[10];
    const float* Whh0  = (const float*)d_in[11];
    const float* bih0  = (const float*)d_in[12];
    const float* bhh0  = (const float*)d_in[13];
    const float* Wih1  = (const float*)d_in[14];
    const float* Whh1  = (const float*)d_in[15];
    const float* bih1  = (const float*)d_in[16];
    const float* bhh1  = (const float*)d_in[17];
    const float* Wlin  = (const float*)d_in[18];
    const float* blin  = (const float*)d_in[19];
    float* out = (float*)d_out;

    k_pass1<<<dim3(64, T_STEPS), 256>>>(ei);

    {
        void* args[] = { (void*)&ei };
        launch_pdl((const void*)k_pass2, dim3(64, T_STEPS), dim3(256), args);
    }
    {
        void* args[] = { (void*)&x, (void*)&Wl1, (void*)&attl1, (void*)&attr1,
                         (void*)&b1, (void*)&Wl2, (void*)&attl2, (void*)&attr2,
                         (void*)&b2 };
        launch_pdl((const void*)k_gat1, dim3(MAX_SLOTS, T_STEPS), dim3(HID), args);
    }
    {
        void* args[] = { (void*)&Wih0, (void*)&Whh0, (void*)&bih0, (void*)&bhh0,
                         (void*)&Wih1, (void*)&Whh1, (void*)&bih1, (void*)&bhh1,
                         (void*)&Wlin, (void*)&blin, (void*)&out };
        launch_pdl((const void*)k_lstm_cl, dim3(128), dim3(512), args, 4);
    }
}